// round 1
// baseline (speedup 1.0000x reference)
#include <cuda_runtime.h>
#include <cstdint>

// ---------------- problem constants ----------------
namespace cfg {
constexpr int   N    = 100000;
constexpr int   D    = 128;
constexpr int   P    = 64;
constexpr int   E    = 3200000;
constexpr int   EPT  = 5000000;
constexpr float INV_EPS = 10.0f;           // 1/0.1
constexpr int   ITERS   = 20;
constexpr float A_MARG  = 1.0f / 100000.0f;
constexpr float B_MARG  = 1.0f / 64.0f;
}

// ---------------- device scratch (static, no allocs) ----------------
__device__ float g_deg[cfg::N];                      // deg, then deg^-1/2
__device__ float g_aggr[(size_t)cfg::N * cfg::D];    // scatter target
__device__ float g_xf[(size_t)cfg::N * cfg::D];      // normalized x_adapted
__device__ float g_K[(size_t)cfg::P * cfg::N];       // column-major K[p][n]
__device__ float g_C[(size_t)cfg::P * cfg::N];       // column-major C[p][n]
__device__ float g_u[cfg::N];
__device__ float g_Ktu[cfg::P];
__device__ float g_v[cfg::P];
__device__ float g_pn[cfg::P * cfg::D];              // normalized prompts
__device__ float g_loss;
__device__ unsigned int g_wmax;

// ---------------- helpers ----------------
__device__ __forceinline__ float warpAllReduceSum(float v) {
#pragma unroll
    for (int o = 16; o; o >>= 1) v += __shfl_xor_sync(0xffffffffu, v, o);
    return v;
}

__device__ __forceinline__ void atomic_add_f4(float4* addr, float4 v) {
#if defined(__CUDA_ARCH__) && __CUDA_ARCH__ >= 900
    atomicAdd(addr, v);
#else
    float* f = reinterpret_cast<float*>(addr);
    atomicAdd(f + 0, v.x); atomicAdd(f + 1, v.y);
    atomicAdd(f + 2, v.z); atomicAdd(f + 3, v.w);
#endif
}

// ---------------- kernels ----------------

__global__ void k_zero() {
    size_t idx    = (size_t)blockIdx.x * blockDim.x + threadIdx.x;
    size_t stride = (size_t)gridDim.x * blockDim.x;
    for (size_t i = idx; i < (size_t)cfg::N * cfg::D; i += stride) g_aggr[i] = 0.0f;
    for (size_t i = idx; i < (size_t)cfg::N; i += stride) g_deg[i] = 0.0f;
    if (idx < (size_t)cfg::P) g_Ktu[idx] = 0.0f;
    if (idx == 0) { g_loss = 0.0f; g_wmax = 0u; }
}

__global__ void k_deg(const int* __restrict__ col) {
    int i = blockIdx.x * blockDim.x + threadIdx.x;
    if (i < cfg::E) atomicAdd(&g_deg[col[i]], 1.0f);
}

__global__ void k_dis() {
    int i = blockIdx.x * blockDim.x + threadIdx.x;
    if (i < cfg::N) {
        float d = g_deg[i];
        g_deg[i] = (d > 0.0f) ? rsqrtf(d) : 0.0f;
    }
}

// warp per edge: x_aggr[row] += x[col] * (dis[row]*ew*dis[col])
__global__ void k_scatter(const float* __restrict__ x,
                          const int* __restrict__ row,
                          const int* __restrict__ col,
                          const float* __restrict__ ew) {
    int lane   = threadIdx.x & 31;
    int warpId = (blockIdx.x * blockDim.x + threadIdx.x) >> 5;
    int nWarps = (gridDim.x * blockDim.x) >> 5;
    for (int e = warpId; e < cfg::E; e += nWarps) {
        int r = row[e], c = col[e];
        float nw = g_deg[r] * ew[e] * g_deg[c];
        float4 v = reinterpret_cast<const float4*>(x + (size_t)c * cfg::D)[lane];
        float4 val = make_float4(v.x * nw, v.y * nw, v.z * nw, v.w * nw);
        atomic_add_f4(reinterpret_cast<float4*>(g_aggr + (size_t)r * cfg::D) + lane, val);
    }
}

// normalize prompt tokens (single block)
__global__ void k_pn(const float* __restrict__ pt) {
    int lane = threadIdx.x & 31;
    int w    = threadIdx.x >> 5;
    for (int p = w; p < cfg::P; p += blockDim.x / 32) {
        float4 v = reinterpret_cast<const float4*>(pt + (size_t)p * cfg::D)[lane];
        float ss = warpAllReduceSum(v.x * v.x + v.y * v.y + v.z * v.z + v.w * v.w);
        float inv = 1.0f / fmaxf(sqrtf(ss), 1e-12f);
        float4 o = make_float4(v.x * inv, v.y * inv, v.z * inv, v.w * inv);
        reinterpret_cast<float4*>(g_pn + (size_t)p * cfg::D)[lane] = o;
    }
}

// warp per node: x_struct, normalize, cost/kernel matrices (column-major)
__global__ void k_ck(const float* __restrict__ x, const float* __restrict__ gammap) {
    __shared__ float spn[cfg::P * cfg::D];
    for (int i = threadIdx.x; i < cfg::P * cfg::D; i += blockDim.x) spn[i] = g_pn[i];
    __syncthreads();
    float gm = *gammap;
    int lane   = threadIdx.x & 31;
    int warpId = (blockIdx.x * blockDim.x + threadIdx.x) >> 5;
    int nWarps = (gridDim.x * blockDim.x) >> 5;
    const float4* pn4 = reinterpret_cast<const float4*>(spn);
    for (int n = warpId; n < cfg::N; n += nWarps) {
        float4 xv = reinterpret_cast<const float4*>(x + (size_t)n * cfg::D)[lane];
        float4 ag = reinterpret_cast<const float4*>(g_aggr + (size_t)n * cfg::D)[lane];
        float4 xs;
        xs.x = (1.0f - gm) * xv.x + gm * ag.x;
        xs.y = (1.0f - gm) * xv.y + gm * ag.y;
        xs.z = (1.0f - gm) * xv.z + gm * ag.z;
        xs.w = (1.0f - gm) * xv.w + gm * ag.w;
        float ss = warpAllReduceSum(xs.x * xs.x + xs.y * xs.y + xs.z * xs.z + xs.w * xs.w);
        float inv = 1.0f / fmaxf(sqrtf(ss), 1e-12f);
        xs.x *= inv; xs.y *= inv; xs.z *= inv; xs.w *= inv;
#pragma unroll 4
        for (int p = 0; p < cfg::P; p++) {
            float4 pv = pn4[p * 32 + lane];
            float s = warpAllReduceSum(xs.x * pv.x + xs.y * pv.y + xs.z * pv.z + xs.w * pv.w);
            if (lane == 0) {
                g_K[(size_t)p * cfg::N + n] = __expf((s - 1.0f) * cfg::INV_EPS);
                g_C[(size_t)p * cfg::N + n] = 1.0f - s;
            }
        }
    }
}

// tiny: v = b/(Ktu+1e-30), re-zero Ktu for next accumulation
__global__ void k_v() {
    int p = threadIdx.x;
    if (p < cfg::P) {
        g_v[p] = cfg::B_MARG / (g_Ktu[p] + 1e-30f);
        g_Ktu[p] = 0.0f;
    }
}

// fused: u = a/(K v + 1e-30); accumulate Ktu_next = K^T u   (one pass over K)
__global__ void k_ua(int init) {
    __shared__ float sv[cfg::P];
    __shared__ float sKtu[cfg::P];
    if (threadIdx.x < cfg::P) {
        sv[threadIdx.x]   = init ? 0.0f : g_v[threadIdx.x];
        sKtu[threadIdx.x] = 0.0f;
    }
    __syncthreads();
    int lane   = threadIdx.x & 31;
    int warpId = (blockIdx.x * blockDim.x + threadIdx.x) >> 5;
    int nWarps = (gridDim.x * blockDim.x) >> 5;
    for (int base = warpId * 32; base < cfg::N; base += nWarps * 32) {
        int n = base + lane;
        bool act = (n < cfg::N);
        int nn = act ? n : 0;
        float u;
        if (init) {
            u = cfg::A_MARG;
        } else {
            float kv = 0.0f;
#pragma unroll 8
            for (int p = 0; p < cfg::P; p++) kv += g_K[(size_t)p * cfg::N + nn] * sv[p];
            u = cfg::A_MARG / (kv + 1e-30f);
        }
        if (act) g_u[n] = u;
        float ua = act ? u : 0.0f;
#pragma unroll 8
        for (int p = 0; p < cfg::P; p++) {
            float t = ua * g_K[(size_t)p * cfg::N + nn];   // L1 hit (2nd touch)
            t = warpAllReduceSum(t);
            if (lane == 0) atomicAdd(&sKtu[p], t);
        }
    }
    __syncthreads();
    if (threadIdx.x < cfg::P) atomicAdd(&g_Ktu[threadIdx.x], sKtu[threadIdx.x]);
}

// warp per node: prompt message, ot_loss, x_adapted -> out, xf = l2norm(x_adapted)
__global__ void k_final(const float* __restrict__ x, const float* __restrict__ pt,
                        const float* __restrict__ alphap, float* __restrict__ out) {
    __shared__ float spt[cfg::P * cfg::D];
    __shared__ float sv[cfg::P];
    __shared__ float sLoss;
    for (int i = threadIdx.x; i < cfg::P * cfg::D; i += blockDim.x) spt[i] = pt[i];
    if (threadIdx.x < cfg::P) sv[threadIdx.x] = g_v[threadIdx.x];
    if (threadIdx.x == 0) sLoss = 0.0f;
    __syncthreads();
    float coef = (*alphap) * (float)cfg::N;
    int lane   = threadIdx.x & 31;
    int warpId = (blockIdx.x * blockDim.x + threadIdx.x) >> 5;
    int nWarps = (gridDim.x * blockDim.x) >> 5;
    const float4* spt4 = reinterpret_cast<const float4*>(spt);
    float lacc = 0.0f;
    for (int n = warpId; n < cfg::N; n += nWarps) {
        float u = g_u[n];
        float4 m = make_float4(0.f, 0.f, 0.f, 0.f);
        float lossn = 0.0f;
#pragma unroll 8
        for (int p = 0; p < cfg::P; p++) {
            float k  = g_K[(size_t)p * cfg::N + n];   // broadcast
            float kv = k * sv[p];
            float4 pv = spt4[p * 32 + lane];
            m.x += kv * pv.x; m.y += kv * pv.y; m.z += kv * pv.z; m.w += kv * pv.w;
            lossn += kv * g_C[(size_t)p * cfg::N + n]; // broadcast
        }
        lacc += u * lossn;   // identical on all lanes; lane0 commits below
        float4 xv = reinterpret_cast<const float4*>(x + (size_t)n * cfg::D)[lane];
        float cu = coef * u;
        float4 xa = make_float4(xv.x + cu * m.x, xv.y + cu * m.y,
                                xv.z + cu * m.z, xv.w + cu * m.w);
        reinterpret_cast<float4*>(out + (size_t)n * cfg::D)[lane] = xa;
        float ss = warpAllReduceSum(xa.x * xa.x + xa.y * xa.y + xa.z * xa.z + xa.w * xa.w);
        float inv = 1.0f / fmaxf(sqrtf(ss), 1e-12f);
        reinterpret_cast<float4*>(g_xf + (size_t)n * cfg::D)[lane] =
            make_float4(xa.x * inv, xa.y * inv, xa.z * inv, xa.w * inv);
    }
    if (lane == 0) atomicAdd(&sLoss, lacc);
    __syncthreads();
    if (threadIdx.x == 0) atomicAdd(&g_loss, sLoss);
}

// warp per prompt-edge: w = relu(dot(xf[r], xf[c])); track max
__global__ void k_edge(const int* __restrict__ prow, const int* __restrict__ pcol,
                       float* __restrict__ outw) {
    __shared__ unsigned int smax;
    if (threadIdx.x == 0) smax = 0u;
    __syncthreads();
    int lane   = threadIdx.x & 31;
    int warpId = (blockIdx.x * blockDim.x + threadIdx.x) >> 5;
    int nWarps = (gridDim.x * blockDim.x) >> 5;
    float lmax = 0.0f;
    for (int e = warpId; e < cfg::EPT; e += nWarps) {
        int r = prow[e], c = pcol[e];
        float4 a = reinterpret_cast<const float4*>(g_xf + (size_t)r * cfg::D)[lane];
        float4 b = reinterpret_cast<const float4*>(g_xf + (size_t)c * cfg::D)[lane];
        float t = a.x * b.x + a.y * b.y + a.z * b.z + a.w * b.w;
#pragma unroll
        for (int o = 16; o; o >>= 1) t += __shfl_down_sync(0xffffffffu, t, o);
        if (lane == 0) {
            float w = fmaxf(t, 0.0f);
            outw[e] = w;
            lmax = fmaxf(lmax, w);
        }
    }
    if (lane == 0) atomicMax(&smax, __float_as_uint(lmax));
    __syncthreads();
    if (threadIdx.x == 0) atomicMax(&g_wmax, smax);
}

// scale w in place; emit ot_loss
__global__ void k_scale(float* __restrict__ out) {
    float inv = 1.0f / (__uint_as_float(g_wmax) + 1e-8f);
    float* w = out + (size_t)cfg::N * cfg::D + 1;
    size_t idx    = (size_t)blockIdx.x * blockDim.x + threadIdx.x;
    size_t stride = (size_t)gridDim.x * blockDim.x;
    for (size_t e = idx; e < (size_t)cfg::EPT; e += stride) w[e] *= inv;
    if (blockIdx.x == 0 && threadIdx.x == 0) out[(size_t)cfg::N * cfg::D] = g_loss;
}

// ---------------- launch ----------------
extern "C" void kernel_launch(void* const* d_in, const int* in_sizes, int n_in,
                              void* d_out, int out_size) {
    const float* x     = (const float*)d_in[0];
    const int*   ei    = (const int*)d_in[1];
    const float* ew    = (const float*)d_in[2];
    const int*   pei   = (const int*)d_in[3];
    const float* pt    = (const float*)d_in[4];
    const float* alpha = (const float*)d_in[5];
    const float* gamma = (const float*)d_in[6];
    float* out = (float*)d_out;

    const int* row  = ei;
    const int* col  = ei + cfg::E;
    const int* prow = pei;
    const int* pcol = pei + cfg::EPT;

    k_zero<<<4096, 256>>>();
    k_deg<<<(cfg::E + 255) / 256, 256>>>(col);
    k_dis<<<(cfg::N + 255) / 256, 256>>>();
    k_scatter<<<8192, 256>>>(x, row, col, ew);
    k_pn<<<1, 256>>>(pt);
    k_ck<<<2048, 256>>>(x, gamma);

    k_ua<<<512, 256>>>(1);                 // Ktu = K^T a   (u0 = a)
    for (int it = 0; it < cfg::ITERS; ++it) {
        k_v<<<1, 64>>>();                  // v = b/(Ktu);  Ktu = 0
        k_ua<<<512, 256>>>(0);             // u = a/(K v);  Ktu += K^T u
    }

    k_final<<<2048, 256>>>(x, pt, alpha, out);
    k_edge<<<8192, 256>>>(prow, pcol, out + (size_t)cfg::N * cfg::D + 1);
    k_scale<<<4096, 256>>>(out);
}

// round 2
// speedup vs baseline: 1.6136x; 1.6136x over previous
#include <cuda_runtime.h>
#include <cuda_fp16.h>
#include <cstdint>

// ---------------- problem constants ----------------
namespace cfg {
constexpr int   N    = 100000;
constexpr int   D    = 128;
constexpr int   P    = 64;
constexpr int   E    = 3200000;
constexpr int   EPT  = 5000000;
constexpr float INV_EPS = 10.0f;           // 1/0.1
constexpr int   ITERS   = 20;
constexpr float A_MARG  = 1.0f / 100000.0f;
constexpr float B_MARG  = 1.0f / 64.0f;
}

// ---------------- device scratch (static, no allocs) ----------------
__device__ float g_deg[cfg::N];                      // deg, then deg^-1/2
__device__ float g_aggr[(size_t)cfg::N * cfg::D];    // scatter target
__device__ __half g_xfh[(size_t)cfg::N * cfg::D];    // normalized x_adapted (fp16)
__device__ float g_K[(size_t)cfg::P * cfg::N];       // column-major K[p][n]
__device__ float g_C[(size_t)cfg::P * cfg::N];       // column-major C[p][n]
__device__ float g_u[cfg::N];
__device__ float g_Ktu3[3][cfg::P];                  // triple-buffered K^T u
__device__ float g_v[cfg::P];
__device__ float g_pn[cfg::P * cfg::D];              // normalized prompts
__device__ float g_loss;
__device__ unsigned int g_wmax;

// ---------------- helpers ----------------
__device__ __forceinline__ float warpAllReduceSum(float v) {
#pragma unroll
    for (int o = 16; o; o >>= 1) v += __shfl_xor_sync(0xffffffffu, v, o);
    return v;
}

__device__ __forceinline__ void atomic_add_f4(float4* addr, float4 v) {
#if defined(__CUDA_ARCH__) && __CUDA_ARCH__ >= 900
    atomicAdd(addr, v);
#else
    float* f = reinterpret_cast<float*>(addr);
    atomicAdd(f + 0, v.x); atomicAdd(f + 1, v.y);
    atomicAdd(f + 2, v.z); atomicAdd(f + 3, v.w);
#endif
}

// ---------------- kernels ----------------

__global__ void k_zero() {
    size_t idx    = (size_t)blockIdx.x * blockDim.x + threadIdx.x;
    size_t stride = (size_t)gridDim.x * blockDim.x;
    for (size_t i = idx; i < (size_t)cfg::N * cfg::D; i += stride) g_aggr[i] = 0.0f;
    for (size_t i = idx; i < (size_t)cfg::N; i += stride) g_deg[i] = 0.0f;
    if (idx < (size_t)(3 * cfg::P)) g_Ktu3[idx / cfg::P][idx % cfg::P] = 0.0f;
    if (idx == 0) { g_loss = 0.0f; g_wmax = 0u; }
}

__global__ void k_deg(const int* __restrict__ col) {
    int i = blockIdx.x * blockDim.x + threadIdx.x;
    if (i < cfg::E) atomicAdd(&g_deg[col[i]], 1.0f);
}

__global__ void k_dis() {
    int i = blockIdx.x * blockDim.x + threadIdx.x;
    if (i < cfg::N) {
        float d = g_deg[i];
        g_deg[i] = (d > 0.0f) ? rsqrtf(d) : 0.0f;
    }
}

// warp per edge: x_aggr[row] += x[col] * (dis[row]*ew*dis[col])
__global__ void k_scatter(const float* __restrict__ x,
                          const int* __restrict__ row,
                          const int* __restrict__ col,
                          const float* __restrict__ ew) {
    int lane   = threadIdx.x & 31;
    int warpId = (blockIdx.x * blockDim.x + threadIdx.x) >> 5;
    int nWarps = (gridDim.x * blockDim.x) >> 5;
    for (int e = warpId; e < cfg::E; e += nWarps) {
        int r = row[e], c = col[e];
        float nw = g_deg[r] * ew[e] * g_deg[c];
        float4 v = reinterpret_cast<const float4*>(x + (size_t)c * cfg::D)[lane];
        float4 val = make_float4(v.x * nw, v.y * nw, v.z * nw, v.w * nw);
        atomic_add_f4(reinterpret_cast<float4*>(g_aggr + (size_t)r * cfg::D) + lane, val);
    }
}

// normalize prompt tokens (single block)
__global__ void k_pn(const float* __restrict__ pt) {
    int lane = threadIdx.x & 31;
    int w    = threadIdx.x >> 5;
    for (int p = w; p < cfg::P; p += blockDim.x / 32) {
        float4 v = reinterpret_cast<const float4*>(pt + (size_t)p * cfg::D)[lane];
        float ss = warpAllReduceSum(v.x * v.x + v.y * v.y + v.z * v.z + v.w * v.w);
        float inv = 1.0f / fmaxf(sqrtf(ss), 1e-12f);
        float4 o = make_float4(v.x * inv, v.y * inv, v.z * inv, v.w * inv);
        reinterpret_cast<float4*>(g_pn + (size_t)p * cfg::D)[lane] = o;
    }
}

// Fused: per block of 128 nodes, build normalized xs in swizzled smem, then
// register-tiled GEMM against pn -> K, C column-major.
// smem: xs_s [128 k][128 n-swizzled] (64KB) + pn_s [128 k][64 p] (32KB) = 96KB
__global__ void k_ck(const float* __restrict__ x, const float* __restrict__ gammap) {
    extern __shared__ float sm[];
    float* xs_s = sm;            // 128*128
    float* pn_s = sm + 16384;    // 128*64
    int t  = threadIdx.x;
    int nb = blockIdx.x * 128;
    float gm = *gammap;

    // load pn into k-major layout
    for (int idx = t; idx < cfg::P * cfg::D; idx += 256) {
        int p = idx >> 7, d = idx & 127;
        pn_s[d * 64 + p] = g_pn[idx];
    }

    // phase1: warp per node, blend + normalize, store swizzled [d][(nl+d)&127]
    int lane = t & 31, w = t >> 5;
    for (int it = 0; it < 16; ++it) {
        int nl = w + 8 * it;            // local node 0..127
        int n  = nb + nl;
        bool act = (n < cfg::N);
        float xs[4];
        float ss = 0.0f;
#pragma unroll
        for (int m = 0; m < 4; ++m) {
            int d = lane + 32 * m;
            float xv = act ? x[(size_t)n * 128 + d] : 0.0f;
            float ag = act ? g_aggr[(size_t)n * 128 + d] : 0.0f;
            xs[m] = (1.0f - gm) * xv + gm * ag;
            ss += xs[m] * xs[m];
        }
        ss = warpAllReduceSum(ss);
        float inv = 1.0f / fmaxf(sqrtf(ss), 1e-12f);
#pragma unroll
        for (int m = 0; m < 4; ++m) {
            int d = lane + 32 * m;
            xs_s[d * 128 + ((nl + d) & 127)] = xs[m] * inv;
        }
    }
    __syncthreads();

    // phase2: GEMM. thread (tx,ty): nodes tx+32i (i<4), prompts ty*8+j (j<8)
    int tx = t & 31, ty = t >> 5;
    float acc[4][8];
#pragma unroll
    for (int i = 0; i < 4; ++i)
#pragma unroll
        for (int j = 0; j < 8; ++j) acc[i][j] = 0.0f;

#pragma unroll 4
    for (int k = 0; k < 128; ++k) {
        float a[4];
#pragma unroll
        for (int i = 0; i < 4; ++i)
            a[i] = xs_s[k * 128 + ((tx + 32 * i + k) & 127)];
        float b[8];
#pragma unroll
        for (int j = 0; j < 8; ++j)
            b[j] = pn_s[k * 64 + ty * 8 + j];
#pragma unroll
        for (int i = 0; i < 4; ++i)
#pragma unroll
            for (int j = 0; j < 8; ++j)
                acc[i][j] += a[i] * b[j];
    }

    // epilogue: K = exp((s-1)*10), C = 1-s, column-major coalesced stores
#pragma unroll
    for (int i = 0; i < 4; ++i) {
        int n = nb + tx + 32 * i;
        if (n < cfg::N) {
#pragma unroll
            for (int j = 0; j < 8; ++j) {
                int p = ty * 8 + j;
                float s = acc[i][j];
                g_K[(size_t)p * cfg::N + n] = __expf((s - 1.0f) * cfg::INV_EPS);
                g_C[(size_t)p * cfg::N + n] = 1.0f - s;
            }
        }
    }
}

// One Sinkhorn iteration per launch. K rows register-resident, read once.
// Triple-buffered Ktu: read ir, accumulate ia, zero iz.
__global__ void k_ua(int ir, int ia, int iz, int init) {
    __shared__ float sv[cfg::P];
    __shared__ float sKtu[cfg::P];
    int t = threadIdx.x;
    if (t < cfg::P) {
        sKtu[t] = 0.0f;
        g_Ktu3[iz][t] = 0.0f;  // racing identical zero-writes across blocks: fine
        if (!init) {
            float v = cfg::B_MARG / (g_Ktu3[ir][t] + 1e-30f);
            sv[t] = v;
            if (blockIdx.x == 0) g_v[t] = v;
        }
    }
    __syncthreads();

    int n = blockIdx.x * 256 + t;
    bool act = (n < cfg::N);
    int nn = act ? n : 0;

    float kreg[64];
#pragma unroll
    for (int p = 0; p < 64; ++p) kreg[p] = g_K[(size_t)p * cfg::N + nn];

    float u;
    if (init) {
        u = cfg::A_MARG;
    } else {
        float kv = 0.0f;
#pragma unroll
        for (int p = 0; p < 64; ++p) kv += kreg[p] * sv[p];
        u = cfg::A_MARG / (kv + 1e-30f);
    }
    if (act) g_u[n] = u;
    float ua = act ? u : 0.0f;
#pragma unroll
    for (int p = 0; p < 64; ++p) kreg[p] *= ua;

    // packed butterfly reduce: 64 values over 32 lanes -> lane holds p=2*lane,2*lane+1
    int lane = t & 31;
#pragma unroll
    for (int k = 0; k < 5; ++k) {
        int off = 16 >> k;
        int c   = 32 >> k;
        bool up = (lane & off) != 0;
#pragma unroll
        for (int i = 0; i < 32; ++i) {
            if (i < c) {
                float mine  = up ? kreg[i + c] : kreg[i];
                float other = up ? kreg[i]     : kreg[i + c];
                kreg[i] = mine + __shfl_xor_sync(0xffffffffu, other, off);
            }
        }
    }
    atomicAdd(&sKtu[2 * lane],     kreg[0]);
    atomicAdd(&sKtu[2 * lane + 1], kreg[1]);
    __syncthreads();
    if (t < cfg::P) atomicAdd(&g_Ktu3[ia][t], sKtu[t]);
}

// warp per node: prompt message, ot_loss, x_adapted -> out, xf(half) = l2norm
__global__ void k_final(const float* __restrict__ x, const float* __restrict__ pt,
                        const float* __restrict__ alphap, float* __restrict__ out) {
    __shared__ float spt[cfg::P * cfg::D];
    __shared__ float sv[cfg::P];
    __shared__ float sLoss;
    for (int i = threadIdx.x; i < cfg::P * cfg::D; i += blockDim.x) spt[i] = pt[i];
    if (threadIdx.x < cfg::P) sv[threadIdx.x] = g_v[threadIdx.x];
    if (threadIdx.x == 0) sLoss = 0.0f;
    __syncthreads();
    float coef = (*alphap) * (float)cfg::N;
    int lane   = threadIdx.x & 31;
    int warpId = (blockIdx.x * blockDim.x + threadIdx.x) >> 5;
    int nWarps = (gridDim.x * blockDim.x) >> 5;
    const float4* spt4 = reinterpret_cast<const float4*>(spt);
    float lacc = 0.0f;
    for (int n = warpId; n < cfg::N; n += nWarps) {
        float u = g_u[n];
        float4 m = make_float4(0.f, 0.f, 0.f, 0.f);
        float lossn = 0.0f;
#pragma unroll 8
        for (int p = 0; p < cfg::P; p++) {
            float k  = g_K[(size_t)p * cfg::N + n];   // broadcast
            float kv = k * sv[p];
            float4 pv = spt4[p * 32 + lane];
            m.x += kv * pv.x; m.y += kv * pv.y; m.z += kv * pv.z; m.w += kv * pv.w;
            lossn += kv * g_C[(size_t)p * cfg::N + n]; // broadcast
        }
        lacc += u * lossn;
        float4 xv = reinterpret_cast<const float4*>(x + (size_t)n * cfg::D)[lane];
        float cu = coef * u;
        float4 xa = make_float4(xv.x + cu * m.x, xv.y + cu * m.y,
                                xv.z + cu * m.z, xv.w + cu * m.w);
        reinterpret_cast<float4*>(out + (size_t)n * cfg::D)[lane] = xa;
        float ss = warpAllReduceSum(xa.x * xa.x + xa.y * xa.y + xa.z * xa.z + xa.w * xa.w);
        float inv = 1.0f / fmaxf(sqrtf(ss), 1e-12f);
        __half2 h01 = __floats2half2_rn(xa.x * inv, xa.y * inv);
        __half2 h23 = __floats2half2_rn(xa.z * inv, xa.w * inv);
        uint2 pk;
        pk.x = *reinterpret_cast<unsigned*>(&h01);
        pk.y = *reinterpret_cast<unsigned*>(&h23);
        reinterpret_cast<uint2*>(g_xfh)[(size_t)n * 32 + lane] = pk;
    }
    if (lane == 0) atomicAdd(&sLoss, lacc);
    __syncthreads();
    if (threadIdx.x == 0) atomicAdd(&g_loss, sLoss);
}

__device__ __forceinline__ float dot8h(uint4 a, uint4 b) {
    const unsigned* pa = &a.x;
    const unsigned* pb = &b.x;
    float s = 0.0f;
#pragma unroll
    for (int i = 0; i < 4; ++i) {
        float2 fa = __half22float2(*reinterpret_cast<const __half2*>(pa + i));
        float2 fb = __half22float2(*reinterpret_cast<const __half2*>(pb + i));
        s += fa.x * fb.x + fa.y * fb.y;
    }
    return s;
}

// half-warp (16 lanes) per prompt-edge on fp16 xf: w = relu(dot); track max
__global__ void k_edge(const int* __restrict__ prow, const int* __restrict__ pcol,
                       float* __restrict__ outw) {
    __shared__ unsigned int smax;
    if (threadIdx.x == 0) smax = 0u;
    __syncthreads();
    int t    = threadIdx.x;
    int lane = t & 31;
    int sub  = lane >> 4;       // 0/1: which edge within the warp
    int sl   = lane & 15;       // lane within half-warp
    int wid  = (blockIdx.x * blockDim.x + t) >> 5;
    int nW   = (gridDim.x * blockDim.x) >> 5;
    const uint4* xf4 = reinterpret_cast<const uint4*>(g_xfh);
    float lmax = 0.0f;
    for (int e0 = wid * 2; e0 < cfg::EPT; e0 += nW * 2) {
        int e = e0 + sub;
        float ts = 0.0f;
        bool act = (e < cfg::EPT);
        if (act) {
            int r = prow[e], c = pcol[e];
            uint4 av = xf4[(size_t)r * 16 + sl];
            uint4 bv = xf4[(size_t)c * 16 + sl];
            ts = dot8h(av, bv);
        }
#pragma unroll
        for (int o = 8; o; o >>= 1) ts += __shfl_xor_sync(0xffffffffu, ts, o);
        if (sl == 0 && act) {
            float wv = fmaxf(ts, 0.0f);
            outw[e] = wv;
            lmax = fmaxf(lmax, wv);
        }
    }
    atomicMax(&smax, __float_as_uint(lmax));
    __syncthreads();
    if (threadIdx.x == 0) atomicMax(&g_wmax, smax);
}

// scale w in place; emit ot_loss
__global__ void k_scale(float* __restrict__ out) {
    float inv = 1.0f / (__uint_as_float(g_wmax) + 1e-8f);
    float* w = out + (size_t)cfg::N * cfg::D + 1;
    size_t idx    = (size_t)blockIdx.x * blockDim.x + threadIdx.x;
    size_t stride = (size_t)gridDim.x * blockDim.x;
    for (size_t e = idx; e < (size_t)cfg::EPT; e += stride) w[e] *= inv;
    if (blockIdx.x == 0 && threadIdx.x == 0) out[(size_t)cfg::N * cfg::D] = g_loss;
}

// ---------------- launch ----------------
extern "C" void kernel_launch(void* const* d_in, const int* in_sizes, int n_in,
                              void* d_out, int out_size) {
    const float* x     = (const float*)d_in[0];
    const int*   ei    = (const int*)d_in[1];
    const float* ew    = (const float*)d_in[2];
    const int*   pei   = (const int*)d_in[3];
    const float* pt    = (const float*)d_in[4];
    const float* alpha = (const float*)d_in[5];
    const float* gamma = (const float*)d_in[6];
    float* out = (float*)d_out;

    const int* row  = ei;
    const int* col  = ei + cfg::E;
    const int* prow = pei;
    const int* pcol = pei + cfg::EPT;

    static int smem_set = 0;
    (void)smem_set;
    cudaFuncSetAttribute(k_ck, cudaFuncAttributeMaxDynamicSharedMemorySize, 98304);

    k_zero<<<4096, 256>>>();
    k_deg<<<(cfg::E + 255) / 256, 256>>>(col);
    k_dis<<<(cfg::N + 255) / 256, 256>>>();
    k_scatter<<<8192, 256>>>(x, row, col, ew);
    k_pn<<<1, 256>>>(pt);
    k_ck<<<(cfg::N + 127) / 128, 256, 98304>>>(x, gamma);

    // Sinkhorn: launch j=0 init (Ktu = K^T a), then 20 full iterations
    for (int j = 0; j <= cfg::ITERS; ++j) {
        int ir = j % 3, ia = (j + 1) % 3, iz = (j + 2) % 3;
        k_ua<<<(cfg::N + 255) / 256, 256>>>(ir, ia, iz, j == 0 ? 1 : 0);
    }

    k_final<<<2048, 256>>>(x, pt, alpha, out);
    k_edge<<<8192, 256>>>(prow, pcol, out + (size_t)cfg::N * cfg::D + 1);
    k_scale<<<4096, 256>>>(out);
}

// round 3
// speedup vs baseline: 1.7676x; 1.0954x over previous
#include <cuda_runtime.h>
#include <cuda_fp16.h>
#include <cstdint>

// ---------------- problem constants ----------------
namespace cfg {
constexpr int   N    = 100000;
constexpr int   D    = 128;
constexpr int   P    = 64;
constexpr int   E    = 3200000;
constexpr int   EPT  = 5000000;
constexpr float INV_EPS = 10.0f;           // 1/0.1
constexpr int   ITERS   = 20;
constexpr float A_MARG  = 1.0f / 100000.0f;
constexpr float B_MARG  = 1.0f / 64.0f;
}

// ---------------- device scratch (static, no allocs) ----------------
__device__ int   g_cnt[cfg::N];                      // row histogram (CSR)
__device__ int   g_degc[cfg::N];                     // col histogram (GCN deg)
__device__ float g_dis[cfg::N];                      // deg^-1/2
__device__ int   g_off[cfg::N];                      // CSR segment base
__device__ int   g_cursor[cfg::N];                   // CSR fill cursor
__device__ int   g_ecol[cfg::E];                     // CSR payload: col
__device__ float g_enw[cfg::E];                      // CSR payload: norm weight
__device__ int   g_total;                            // segment allocator
__device__ float g_aggr[(size_t)cfg::N * cfg::D];    // aggregation result
__device__ __half g_xfh[(size_t)cfg::N * cfg::D];    // normalized x_adapted (fp16)
__device__ float g_K[(size_t)cfg::P * cfg::N];       // column-major K[p][n]
__device__ float g_C[(size_t)cfg::P * cfg::N];       // column-major C[p][n]
__device__ float g_u[cfg::N];
__device__ float g_Ktu3[3][cfg::P];                  // triple-buffered K^T u
__device__ float g_v[cfg::P];
__device__ float g_pn[cfg::P * cfg::D];              // normalized prompts
__device__ float g_loss;
__device__ unsigned int g_wmax;

// ---------------- helpers ----------------
__device__ __forceinline__ float warpAllReduceSum(float v) {
#pragma unroll
    for (int o = 16; o; o >>= 1) v += __shfl_xor_sync(0xffffffffu, v, o);
    return v;
}

// ---------------- kernels ----------------

__global__ void k_zero() {
    size_t idx    = (size_t)blockIdx.x * blockDim.x + threadIdx.x;
    size_t stride = (size_t)gridDim.x * blockDim.x;
    for (size_t i = idx; i < (size_t)cfg::N; i += stride) { g_cnt[i] = 0; g_degc[i] = 0; }
    if (idx < (size_t)(3 * cfg::P)) g_Ktu3[idx / cfg::P][idx % cfg::P] = 0.0f;
    if (idx == 0) { g_loss = 0.0f; g_wmax = 0u; g_total = 0; }
}

// histograms: row buckets (CSR) and col degree (GCN norm)
__global__ void k_count(const int* __restrict__ row, const int* __restrict__ col) {
    int i = blockIdx.x * blockDim.x + threadIdx.x;
    if (i < cfg::E) {
        atomicAdd(&g_cnt[row[i]], 1);
        atomicAdd(&g_degc[col[i]], 1);
    }
}

// per node: deg^-1/2 and CSR segment allocation (ticket; order irrelevant)
__global__ void k_node() {
    int i = blockIdx.x * blockDim.x + threadIdx.x;
    if (i < cfg::N) {
        int d = g_degc[i];
        g_dis[i] = (d > 0) ? rsqrtf((float)d) : 0.0f;
        int c = g_cnt[i];
        int base = atomicAdd(&g_total, c);
        g_off[i] = base;
        g_cursor[i] = base;
    }
}

// per edge: compute normalized weight, drop payload into row's CSR segment
__global__ void k_fill(const int* __restrict__ row, const int* __restrict__ col,
                       const float* __restrict__ ew) {
    int i = blockIdx.x * blockDim.x + threadIdx.x;
    if (i < cfg::E) {
        int r = row[i], c = col[i];
        float nw = g_dis[r] * ew[i] * g_dis[c];
        int pos = atomicAdd(&g_cursor[r], 1);
        g_ecol[pos] = c;
        g_enw[pos]  = nw;
    }
}

// warp per node: pull-aggregate x[col]*nw over the node's CSR segment.
// One 512B write per node, no atomics.
__global__ void k_aggr(const float* __restrict__ x) {
    int lane   = threadIdx.x & 31;
    int n      = (blockIdx.x * blockDim.x + threadIdx.x) >> 5;
    if (n >= cfg::N) return;
    int base = g_off[n];
    int cnt  = g_cnt[n];
    const float4* x4 = reinterpret_cast<const float4*>(x);
    float4 acc = make_float4(0.f, 0.f, 0.f, 0.f);
    int j = 0;
    for (; j + 2 <= cnt; j += 2) {
        int   c0 = g_ecol[base + j],     c1 = g_ecol[base + j + 1];
        float w0 = g_enw[base + j],      w1 = g_enw[base + j + 1];
        float4 v0 = x4[(size_t)c0 * 32 + lane];
        float4 v1 = x4[(size_t)c1 * 32 + lane];
        acc.x += w0 * v0.x + w1 * v1.x;
        acc.y += w0 * v0.y + w1 * v1.y;
        acc.z += w0 * v0.z + w1 * v1.z;
        acc.w += w0 * v0.w + w1 * v1.w;
    }
    if (j < cnt) {
        int   c0 = g_ecol[base + j];
        float w0 = g_enw[base + j];
        float4 v0 = x4[(size_t)c0 * 32 + lane];
        acc.x += w0 * v0.x; acc.y += w0 * v0.y;
        acc.z += w0 * v0.z; acc.w += w0 * v0.w;
    }
    reinterpret_cast<float4*>(g_aggr)[(size_t)n * 32 + lane] = acc;
}

// normalize prompt tokens (single block)
__global__ void k_pn(const float* __restrict__ pt) {
    int lane = threadIdx.x & 31;
    int w    = threadIdx.x >> 5;
    for (int p = w; p < cfg::P; p += blockDim.x / 32) {
        float4 v = reinterpret_cast<const float4*>(pt + (size_t)p * cfg::D)[lane];
        float ss = warpAllReduceSum(v.x * v.x + v.y * v.y + v.z * v.z + v.w * v.w);
        float inv = 1.0f / fmaxf(sqrtf(ss), 1e-12f);
        float4 o = make_float4(v.x * inv, v.y * inv, v.z * inv, v.w * inv);
        reinterpret_cast<float4*>(g_pn + (size_t)p * cfg::D)[lane] = o;
    }
}

// Fused: per block of 128 nodes, build normalized xs in swizzled smem, then
// register-tiled GEMM against pn -> K, C column-major.
__global__ void k_ck(const float* __restrict__ x, const float* __restrict__ gammap) {
    extern __shared__ float sm[];
    float* xs_s = sm;            // 128*128
    float* pn_s = sm + 16384;    // 128*64
    int t  = threadIdx.x;
    int nb = blockIdx.x * 128;
    float gm = *gammap;

    for (int idx = t; idx < cfg::P * cfg::D; idx += 256) {
        int p = idx >> 7, d = idx & 127;
        pn_s[d * 64 + p] = g_pn[idx];
    }

    int lane = t & 31, w = t >> 5;
    for (int it = 0; it < 16; ++it) {
        int nl = w + 8 * it;
        int n  = nb + nl;
        bool act = (n < cfg::N);
        float xs[4];
        float ss = 0.0f;
#pragma unroll
        for (int m = 0; m < 4; ++m) {
            int d = lane + 32 * m;
            float xv = act ? x[(size_t)n * 128 + d] : 0.0f;
            float ag = act ? g_aggr[(size_t)n * 128 + d] : 0.0f;
            xs[m] = (1.0f - gm) * xv + gm * ag;
            ss += xs[m] * xs[m];
        }
        ss = warpAllReduceSum(ss);
        float inv = 1.0f / fmaxf(sqrtf(ss), 1e-12f);
#pragma unroll
        for (int m = 0; m < 4; ++m) {
            int d = lane + 32 * m;
            xs_s[d * 128 + ((nl + d) & 127)] = xs[m] * inv;
        }
    }
    __syncthreads();

    int tx = t & 31, ty = t >> 5;
    float acc[4][8];
#pragma unroll
    for (int i = 0; i < 4; ++i)
#pragma unroll
        for (int j = 0; j < 8; ++j) acc[i][j] = 0.0f;

#pragma unroll 4
    for (int k = 0; k < 128; ++k) {
        float a[4];
#pragma unroll
        for (int i = 0; i < 4; ++i)
            a[i] = xs_s[k * 128 + ((tx + 32 * i + k) & 127)];
        float b[8];
#pragma unroll
        for (int j = 0; j < 8; ++j)
            b[j] = pn_s[k * 64 + ty * 8 + j];
#pragma unroll
        for (int i = 0; i < 4; ++i)
#pragma unroll
            for (int j = 0; j < 8; ++j)
                acc[i][j] += a[i] * b[j];
    }

#pragma unroll
    for (int i = 0; i < 4; ++i) {
        int n = nb + tx + 32 * i;
        if (n < cfg::N) {
#pragma unroll
            for (int j = 0; j < 8; ++j) {
                int p = ty * 8 + j;
                float s = acc[i][j];
                g_K[(size_t)p * cfg::N + n] = __expf((s - 1.0f) * cfg::INV_EPS);
                g_C[(size_t)p * cfg::N + n] = 1.0f - s;
            }
        }
    }
}

// One Sinkhorn iteration per launch. K rows register-resident, read once.
__global__ void k_ua(int ir, int ia, int iz, int init) {
    __shared__ float sv[cfg::P];
    __shared__ float sKtu[cfg::P];
    int t = threadIdx.x;
    if (t < cfg::P) {
        sKtu[t] = 0.0f;
        g_Ktu3[iz][t] = 0.0f;
        if (!init) {
            float v = cfg::B_MARG / (g_Ktu3[ir][t] + 1e-30f);
            sv[t] = v;
            if (blockIdx.x == 0) g_v[t] = v;
        }
    }
    __syncthreads();

    int n = blockIdx.x * 256 + t;
    bool act = (n < cfg::N);
    int nn = act ? n : 0;

    float kreg[64];
#pragma unroll
    for (int p = 0; p < 64; ++p) kreg[p] = g_K[(size_t)p * cfg::N + nn];

    float u;
    if (init) {
        u = cfg::A_MARG;
    } else {
        float kv = 0.0f;
#pragma unroll
        for (int p = 0; p < 64; ++p) kv += kreg[p] * sv[p];
        u = cfg::A_MARG / (kv + 1e-30f);
    }
    if (act) g_u[n] = u;
    float ua = act ? u : 0.0f;
#pragma unroll
    for (int p = 0; p < 64; ++p) kreg[p] *= ua;

    int lane = t & 31;
#pragma unroll
    for (int k = 0; k < 5; ++k) {
        int off = 16 >> k;
        int c   = 32 >> k;
        bool up = (lane & off) != 0;
#pragma unroll
        for (int i = 0; i < 32; ++i) {
            if (i < c) {
                float mine  = up ? kreg[i + c] : kreg[i];
                float other = up ? kreg[i]     : kreg[i + c];
                kreg[i] = mine + __shfl_xor_sync(0xffffffffu, other, off);
            }
        }
    }
    atomicAdd(&sKtu[2 * lane],     kreg[0]);
    atomicAdd(&sKtu[2 * lane + 1], kreg[1]);
    __syncthreads();
    if (t < cfg::P) atomicAdd(&g_Ktu3[ia][t], sKtu[t]);
}

// warp per node: prompt message, ot_loss, x_adapted -> out, xf(half) = l2norm
__global__ void k_final(const float* __restrict__ x, const float* __restrict__ pt,
                        const float* __restrict__ alphap, float* __restrict__ out) {
    __shared__ float spt[cfg::P * cfg::D];
    __shared__ float sv[cfg::P];
    __shared__ float sLoss;
    for (int i = threadIdx.x; i < cfg::P * cfg::D; i += blockDim.x) spt[i] = pt[i];
    if (threadIdx.x < cfg::P) sv[threadIdx.x] = g_v[threadIdx.x];
    if (threadIdx.x == 0) sLoss = 0.0f;
    __syncthreads();
    float coef = (*alphap) * (float)cfg::N;
    int lane   = threadIdx.x & 31;
    int warpId = (blockIdx.x * blockDim.x + threadIdx.x) >> 5;
    int nWarps = (gridDim.x * blockDim.x) >> 5;
    const float4* spt4 = reinterpret_cast<const float4*>(spt);
    float lacc = 0.0f;
    for (int n = warpId; n < cfg::N; n += nWarps) {
        float u = g_u[n];
        float4 m = make_float4(0.f, 0.f, 0.f, 0.f);
        float lossn = 0.0f;
#pragma unroll 8
        for (int p = 0; p < cfg::P; p++) {
            float k  = g_K[(size_t)p * cfg::N + n];
            float kv = k * sv[p];
            float4 pv = spt4[p * 32 + lane];
            m.x += kv * pv.x; m.y += kv * pv.y; m.z += kv * pv.z; m.w += kv * pv.w;
            lossn += kv * g_C[(size_t)p * cfg::N + n];
        }
        lacc += u * lossn;
        float4 xv = reinterpret_cast<const float4*>(x + (size_t)n * cfg::D)[lane];
        float cu = coef * u;
        float4 xa = make_float4(xv.x + cu * m.x, xv.y + cu * m.y,
                                xv.z + cu * m.z, xv.w + cu * m.w);
        reinterpret_cast<float4*>(out + (size_t)n * cfg::D)[lane] = xa;
        float ss = warpAllReduceSum(xa.x * xa.x + xa.y * xa.y + xa.z * xa.z + xa.w * xa.w);
        float inv = 1.0f / fmaxf(sqrtf(ss), 1e-12f);
        __half2 h01 = __floats2half2_rn(xa.x * inv, xa.y * inv);
        __half2 h23 = __floats2half2_rn(xa.z * inv, xa.w * inv);
        uint2 pk;
        pk.x = *reinterpret_cast<unsigned*>(&h01);
        pk.y = *reinterpret_cast<unsigned*>(&h23);
        reinterpret_cast<uint2*>(g_xfh)[(size_t)n * 32 + lane] = pk;
    }
    if (lane == 0) atomicAdd(&sLoss, lacc);
    __syncthreads();
    if (threadIdx.x == 0) atomicAdd(&g_loss, sLoss);
}

__device__ __forceinline__ float dot8h(uint4 a, uint4 b) {
    const unsigned* pa = &a.x;
    const unsigned* pb = &b.x;
    float s = 0.0f;
#pragma unroll
    for (int i = 0; i < 4; ++i) {
        float2 fa = __half22float2(*reinterpret_cast<const __half2*>(pa + i));
        float2 fb = __half22float2(*reinterpret_cast<const __half2*>(pb + i));
        s += fa.x * fb.x + fa.y * fb.y;
    }
    return s;
}

// half-warp (16 lanes) per prompt-edge on fp16 xf: w = relu(dot); track max
__global__ void k_edge(const int* __restrict__ prow, const int* __restrict__ pcol,
                       float* __restrict__ outw) {
    __shared__ unsigned int smax;
    if (threadIdx.x == 0) smax = 0u;
    __syncthreads();
    int t    = threadIdx.x;
    int lane = t & 31;
    int sub  = lane >> 4;
    int sl   = lane & 15;
    int wid  = (blockIdx.x * blockDim.x + t) >> 5;
    int nW   = (gridDim.x * blockDim.x) >> 5;
    const uint4* xf4 = reinterpret_cast<const uint4*>(g_xfh);
    float lmax = 0.0f;
    for (int e0 = wid * 2; e0 < cfg::EPT; e0 += nW * 2) {
        int e = e0 + sub;
        float ts = 0.0f;
        bool act = (e < cfg::EPT);
        if (act) {
            int r = prow[e], c = pcol[e];
            uint4 av = xf4[(size_t)r * 16 + sl];
            uint4 bv = xf4[(size_t)c * 16 + sl];
            ts = dot8h(av, bv);
        }
#pragma unroll
        for (int o = 8; o; o >>= 1) ts += __shfl_xor_sync(0xffffffffu, ts, o);
        if (sl == 0 && act) {
            float wv = fmaxf(ts, 0.0f);
            outw[e] = wv;
            lmax = fmaxf(lmax, wv);
        }
    }
    atomicMax(&smax, __float_as_uint(lmax));
    __syncthreads();
    if (threadIdx.x == 0) atomicMax(&g_wmax, smax);
}

// scale w in place; emit ot_loss
__global__ void k_scale(float* __restrict__ out) {
    float inv = 1.0f / (__uint_as_float(g_wmax) + 1e-8f);
    float* w = out + (size_t)cfg::N * cfg::D + 1;
    size_t idx    = (size_t)blockIdx.x * blockDim.x + threadIdx.x;
    size_t stride = (size_t)gridDim.x * blockDim.x;
    for (size_t e = idx; e < (size_t)cfg::EPT; e += stride) w[e] *= inv;
    if (blockIdx.x == 0 && threadIdx.x == 0) out[(size_t)cfg::N * cfg::D] = g_loss;
}

// ---------------- launch ----------------
extern "C" void kernel_launch(void* const* d_in, const int* in_sizes, int n_in,
                              void* d_out, int out_size) {
    const float* x     = (const float*)d_in[0];
    const int*   ei    = (const int*)d_in[1];
    const float* ew    = (const float*)d_in[2];
    const int*   pei   = (const int*)d_in[3];
    const float* pt    = (const float*)d_in[4];
    const float* alpha = (const float*)d_in[5];
    const float* gamma = (const float*)d_in[6];
    float* out = (float*)d_out;

    const int* row  = ei;
    const int* col  = ei + cfg::E;
    const int* prow = pei;
    const int* pcol = pei + cfg::EPT;

    cudaFuncSetAttribute(k_ck, cudaFuncAttributeMaxDynamicSharedMemorySize, 98304);

    k_zero<<<512, 256>>>();
    k_count<<<(cfg::E + 255) / 256, 256>>>(row, col);
    k_node<<<(cfg::N + 255) / 256, 256>>>();
    k_fill<<<(cfg::E + 255) / 256, 256>>>(row, col, ew);
    k_aggr<<<(cfg::N * 32 + 255) / 256, 256>>>(x);
    k_pn<<<1, 256>>>(pt);
    k_ck<<<(cfg::N + 127) / 128, 256, 98304>>>(x, gamma);

    for (int j = 0; j <= cfg::ITERS; ++j) {
        int ir = j % 3, ia = (j + 1) % 3, iz = (j + 2) % 3;
        k_ua<<<(cfg::N + 255) / 256, 256>>>(ir, ia, iz, j == 0 ? 1 : 0);
    }

    k_final<<<2048, 256>>>(x, pt, alpha, out);
    k_edge<<<8192, 256>>>(prow, pcol, out + (size_t)cfg::N * cfg::D + 1);
    k_scale<<<4096, 256>>>(out);
}

// round 4
// speedup vs baseline: 1.7753x; 1.0044x over previous
#include <cuda_runtime.h>
#include <cuda_fp16.h>
#include <cstdint>

// ---------------- problem constants ----------------
namespace cfg {
constexpr int   N    = 100000;
constexpr int   D    = 128;
constexpr int   P    = 64;
constexpr int   E    = 3200000;
constexpr int   EPT  = 5000000;
constexpr float INV_EPS = 10.0f;           // 1/0.1
constexpr int   ITERS   = 20;
constexpr float A_MARG  = 1.0f / 100000.0f;
constexpr float B_MARG  = 1.0f / 64.0f;
}

constexpr int SBLK = 296;   // persistent sinkhorn grid (2 blocks/SM guaranteed)
constexpr int STHR = 256;
constexpr int SNT  = SBLK * STHR;

// ---------------- device scratch (static, no allocs) ----------------
__device__ int   g_cnt[cfg::N];                      // row histogram (CSR)
__device__ int   g_degc[cfg::N];                     // col histogram (GCN deg)
__device__ float g_dis[cfg::N];                      // deg^-1/2
__device__ int   g_off[cfg::N];                      // CSR segment base
__device__ int   g_cursor[cfg::N];                   // CSR fill cursor
__device__ int   g_ecol[cfg::E];                     // CSR payload: col
__device__ float g_enw[cfg::E];                      // CSR payload: norm weight
__device__ int   g_total;                            // segment allocator
__device__ __half g_xh[(size_t)cfg::N * cfg::D];     // fp16 copy of x (gathers)
__device__ float g_aggr[(size_t)cfg::N * cfg::D];    // aggregation result
__device__ __half g_xfh[(size_t)cfg::N * cfg::D];    // normalized x_adapted (fp16)
__device__ float g_K[(size_t)cfg::P * cfg::N];       // column-major K[p][n]
__device__ float g_C[(size_t)cfg::P * cfg::N];       // column-major C[p][n]
__device__ float g_u[cfg::N];
__device__ float g_KtuI[cfg::ITERS + 1][cfg::P];     // per-iteration K^T u buffers
__device__ int   g_barc[cfg::ITERS + 1];             // per-iteration barrier counters
__device__ float g_v[cfg::P];
__device__ float g_pn[cfg::P * cfg::D];              // normalized prompts
__device__ float g_loss;
__device__ unsigned int g_wmax;

// ---------------- helpers ----------------
__device__ __forceinline__ float warpAllReduceSum(float v) {
#pragma unroll
    for (int o = 16; o; o >>= 1) v += __shfl_xor_sync(0xffffffffu, v, o);
    return v;
}

// ---------------- kernels ----------------

__global__ void k_zero() {
    size_t idx    = (size_t)blockIdx.x * blockDim.x + threadIdx.x;
    size_t stride = (size_t)gridDim.x * blockDim.x;
    for (size_t i = idx; i < (size_t)cfg::N; i += stride) { g_cnt[i] = 0; g_degc[i] = 0; }
    if (idx < (size_t)((cfg::ITERS + 1) * cfg::P))
        g_KtuI[idx / cfg::P][idx % cfg::P] = 0.0f;
    if (idx <= (size_t)cfg::ITERS) g_barc[idx] = 0;
    if (idx == 0) { g_loss = 0.0f; g_wmax = 0u; g_total = 0; }
}

// fp16 copy of x for gather traffic reduction
__global__ void k_xh(const float* __restrict__ x) {
    size_t idx    = (size_t)blockIdx.x * blockDim.x + threadIdx.x;
    size_t stride = (size_t)gridDim.x * blockDim.x;
    const float4* x4 = reinterpret_cast<const float4*>(x);
    uint2* xh2 = reinterpret_cast<uint2*>(g_xh);
    size_t total = (size_t)cfg::N * cfg::D / 4;
    for (size_t i = idx; i < total; i += stride) {
        float4 v = x4[i];
        __half2 h0 = __floats2half2_rn(v.x, v.y);
        __half2 h1 = __floats2half2_rn(v.z, v.w);
        uint2 pk;
        pk.x = *reinterpret_cast<unsigned*>(&h0);
        pk.y = *reinterpret_cast<unsigned*>(&h1);
        xh2[i] = pk;
    }
}

// histograms: row buckets (CSR) and col degree (GCN norm)
__global__ void k_count(const int* __restrict__ row, const int* __restrict__ col) {
    int i = blockIdx.x * blockDim.x + threadIdx.x;
    if (i < cfg::E) {
        atomicAdd(&g_cnt[row[i]], 1);
        atomicAdd(&g_degc[col[i]], 1);
    }
}

// per node: deg^-1/2 and CSR segment allocation (ticket; order irrelevant)
__global__ void k_node() {
    int i = blockIdx.x * blockDim.x + threadIdx.x;
    if (i < cfg::N) {
        int d = g_degc[i];
        g_dis[i] = (d > 0) ? rsqrtf((float)d) : 0.0f;
        int c = g_cnt[i];
        int base = atomicAdd(&g_total, c);
        g_off[i] = base;
        g_cursor[i] = base;
    }
}

// per edge: compute normalized weight, drop payload into row's CSR segment
__global__ void k_fill(const int* __restrict__ row, const int* __restrict__ col,
                       const float* __restrict__ ew) {
    int i = blockIdx.x * blockDim.x + threadIdx.x;
    if (i < cfg::E) {
        int r = row[i], c = col[i];
        float nw = g_dis[r] * ew[i] * g_dis[c];
        int pos = atomicAdd(&g_cursor[r], 1);
        g_ecol[pos] = c;
        g_enw[pos]  = nw;
    }
}

// warp per node: pull-aggregate xh[col]*nw over the node's CSR segment (fp16 gathers).
__global__ void k_aggr() {
    int lane = threadIdx.x & 31;
    int n    = (blockIdx.x * blockDim.x + threadIdx.x) >> 5;
    if (n >= cfg::N) return;
    int base = g_off[n];
    int cnt  = g_cnt[n];
    const uint2* xh2 = reinterpret_cast<const uint2*>(g_xh);
    float4 acc = make_float4(0.f, 0.f, 0.f, 0.f);
    for (int j = 0; j < cnt; ++j) {
        int   c0 = g_ecol[base + j];
        float w0 = g_enw[base + j];
        uint2 raw = xh2[(size_t)c0 * 32 + lane];
        float2 f0 = __half22float2(*reinterpret_cast<__half2*>(&raw.x));
        float2 f1 = __half22float2(*reinterpret_cast<__half2*>(&raw.y));
        acc.x += w0 * f0.x; acc.y += w0 * f0.y;
        acc.z += w0 * f1.x; acc.w += w0 * f1.y;
    }
    reinterpret_cast<float4*>(g_aggr)[(size_t)n * 32 + lane] = acc;
}

// normalize prompt tokens (single block)
__global__ void k_pn(const float* __restrict__ pt) {
    int lane = threadIdx.x & 31;
    int w    = threadIdx.x >> 5;
    for (int p = w; p < cfg::P; p += blockDim.x / 32) {
        float4 v = reinterpret_cast<const float4*>(pt + (size_t)p * cfg::D)[lane];
        float ss = warpAllReduceSum(v.x * v.x + v.y * v.y + v.z * v.z + v.w * v.w);
        float inv = 1.0f / fmaxf(sqrtf(ss), 1e-12f);
        float4 o = make_float4(v.x * inv, v.y * inv, v.z * inv, v.w * inv);
        reinterpret_cast<float4*>(g_pn + (size_t)p * cfg::D)[lane] = o;
    }
}

// Fused: per block of 128 nodes, build normalized xs in swizzled smem, then
// register-tiled GEMM against pn -> K, C column-major.
__global__ void k_ck(const float* __restrict__ x, const float* __restrict__ gammap) {
    extern __shared__ float sm[];
    float* xs_s = sm;            // 128*128
    float* pn_s = sm + 16384;    // 128*64
    int t  = threadIdx.x;
    int nb = blockIdx.x * 128;
    float gm = *gammap;

    for (int idx = t; idx < cfg::P * cfg::D; idx += 256) {
        int p = idx >> 7, d = idx & 127;
        pn_s[d * 64 + p] = g_pn[idx];
    }

    int lane = t & 31, w = t >> 5;
    for (int it = 0; it < 16; ++it) {
        int nl = w + 8 * it;
        int n  = nb + nl;
        bool act = (n < cfg::N);
        float xs[4];
        float ss = 0.0f;
#pragma unroll
        for (int m = 0; m < 4; ++m) {
            int d = lane + 32 * m;
            float xv = act ? x[(size_t)n * 128 + d] : 0.0f;
            float ag = act ? g_aggr[(size_t)n * 128 + d] : 0.0f;
            xs[m] = (1.0f - gm) * xv + gm * ag;
            ss += xs[m] * xs[m];
        }
        ss = warpAllReduceSum(ss);
        float inv = 1.0f / fmaxf(sqrtf(ss), 1e-12f);
#pragma unroll
        for (int m = 0; m < 4; ++m) {
            int d = lane + 32 * m;
            xs_s[d * 128 + ((nl + d) & 127)] = xs[m] * inv;
        }
    }
    __syncthreads();

    int tx = t & 31, ty = t >> 5;
    float acc[4][8];
#pragma unroll
    for (int i = 0; i < 4; ++i)
#pragma unroll
        for (int j = 0; j < 8; ++j) acc[i][j] = 0.0f;

#pragma unroll 4
    for (int k = 0; k < 128; ++k) {
        float a[4];
#pragma unroll
        for (int i = 0; i < 4; ++i)
            a[i] = xs_s[k * 128 + ((tx + 32 * i + k) & 127)];
        float b[8];
#pragma unroll
        for (int j = 0; j < 8; ++j)
            b[j] = pn_s[k * 64 + ty * 8 + j];
#pragma unroll
        for (int i = 0; i < 4; ++i)
#pragma unroll
            for (int j = 0; j < 8; ++j)
                acc[i][j] += a[i] * b[j];
    }

#pragma unroll
    for (int i = 0; i < 4; ++i) {
        int n = nb + tx + 32 * i;
        if (n < cfg::N) {
#pragma unroll
            for (int j = 0; j < 8; ++j) {
                int p = ty * 8 + j;
                float s = acc[i][j];
                g_K[(size_t)p * cfg::N + n] = __expf((s - 1.0f) * cfg::INV_EPS);
                g_C[(size_t)p * cfg::N + n] = 1.0f - s;
            }
        }
    }
}

// grid barrier: per-iteration counter (no reuse, no ABA)
__device__ __forceinline__ void gbar(int idx) {
    __syncthreads();
    if (threadIdx.x == 0) {
        __threadfence();
        atomicAdd(&g_barc[idx], 1);
        volatile int* c = &g_barc[idx];
        while (*c < SBLK) { }
        __threadfence();
    }
    __syncthreads();
}

// Persistent Sinkhorn: all 21 passes (init + 20 iterations) in one kernel.
__global__ void __launch_bounds__(STHR, 2) k_sink() {
    __shared__ float sv[cfg::P];
    __shared__ float sKtu[cfg::P];
    int t    = threadIdx.x;
    int lane = t & 31;
    int gtid = blockIdx.x * STHR + t;

    for (int j = 0; j <= cfg::ITERS; ++j) {
        if (j > 0) gbar(j - 1);             // wait for KtuI[j-1] complete
        if (t < cfg::P) {
            sKtu[t] = 0.0f;
            if (j > 0) sv[t] = cfg::B_MARG / (g_KtuI[j - 1][t] + 1e-30f);
        }
        __syncthreads();
        bool last = (j == cfg::ITERS);

#pragma unroll
        for (int rep = 0; rep < 2; ++rep) {
            int n = gtid + rep * SNT;
            bool act = (n < cfg::N);
            int nn = act ? n : 0;
            float kreg[64];
#pragma unroll
            for (int p = 0; p < 64; ++p) kreg[p] = g_K[(size_t)p * cfg::N + nn];
            float u;
            if (j == 0) {
                u = cfg::A_MARG;
            } else {
                float kv = 0.0f;
#pragma unroll
                for (int p = 0; p < 64; ++p) kv += kreg[p] * sv[p];
                u = cfg::A_MARG / (kv + 1e-30f);
            }
            if (last) {
                if (act) g_u[n] = u;
            } else {
                float ua = act ? u : 0.0f;
#pragma unroll
                for (int p = 0; p < 64; ++p) kreg[p] *= ua;
                // packed butterfly: 64 values -> lane holds p=2*lane, 2*lane+1
#pragma unroll
                for (int k = 0; k < 5; ++k) {
                    int off = 16 >> k;
                    int c   = 32 >> k;
                    bool up = (lane & off) != 0;
#pragma unroll
                    for (int i = 0; i < 32; ++i) {
                        if (i < c) {
                            float mine  = up ? kreg[i + c] : kreg[i];
                            float other = up ? kreg[i]     : kreg[i + c];
                            kreg[i] = mine + __shfl_xor_sync(0xffffffffu, other, off);
                        }
                    }
                }
                atomicAdd(&sKtu[2 * lane],     kreg[0]);
                atomicAdd(&sKtu[2 * lane + 1], kreg[1]);
            }
        }

        if (!last) {
            __syncthreads();
            if (t < cfg::P) {
                float old = atomicAdd(&g_KtuI[j][t], sKtu[t]);
                // consume result to force atomic completion before barrier arrive
                if (__float_as_uint(old) == 0xdeadbeefu) sKtu[t] = old;
            }
        } else {
            if (blockIdx.x == 0 && t < cfg::P) g_v[t] = sv[t];
        }
    }
}

// warp per node: prompt message, ot_loss, x_adapted -> out, xf(half) = l2norm
__global__ void k_final(const float* __restrict__ x, const float* __restrict__ pt,
                        const float* __restrict__ alphap, float* __restrict__ out) {
    __shared__ float spt[cfg::P * cfg::D];
    __shared__ float sv[cfg::P];
    __shared__ float sLoss;
    for (int i = threadIdx.x; i < cfg::P * cfg::D; i += blockDim.x) spt[i] = pt[i];
    if (threadIdx.x < cfg::P) sv[threadIdx.x] = g_v[threadIdx.x];
    if (threadIdx.x == 0) sLoss = 0.0f;
    __syncthreads();
    float coef = (*alphap) * (float)cfg::N;
    int lane   = threadIdx.x & 31;
    int warpId = (blockIdx.x * blockDim.x + threadIdx.x) >> 5;
    int nWarps = (gridDim.x * blockDim.x) >> 5;
    const float4* spt4 = reinterpret_cast<const float4*>(spt);
    float lacc = 0.0f;
    for (int n = warpId; n < cfg::N; n += nWarps) {
        float u = g_u[n];
        float4 m = make_float4(0.f, 0.f, 0.f, 0.f);
        float lossn = 0.0f;
#pragma unroll 8
        for (int p = 0; p < cfg::P; p++) {
            float k  = g_K[(size_t)p * cfg::N + n];
            float kv = k * sv[p];
            float4 pv = spt4[p * 32 + lane];
            m.x += kv * pv.x; m.y += kv * pv.y; m.z += kv * pv.z; m.w += kv * pv.w;
            lossn += kv * g_C[(size_t)p * cfg::N + n];
        }
        lacc += u * lossn;
        float4 xv = reinterpret_cast<const float4*>(x + (size_t)n * cfg::D)[lane];
        float cu = coef * u;
        float4 xa = make_float4(xv.x + cu * m.x, xv.y + cu * m.y,
                                xv.z + cu * m.z, xv.w + cu * m.w);
        reinterpret_cast<float4*>(out + (size_t)n * cfg::D)[lane] = xa;
        float ss = warpAllReduceSum(xa.x * xa.x + xa.y * xa.y + xa.z * xa.z + xa.w * xa.w);
        float inv = 1.0f / fmaxf(sqrtf(ss), 1e-12f);
        __half2 h01 = __floats2half2_rn(xa.x * inv, xa.y * inv);
        __half2 h23 = __floats2half2_rn(xa.z * inv, xa.w * inv);
        uint2 pk;
        pk.x = *reinterpret_cast<unsigned*>(&h01);
        pk.y = *reinterpret_cast<unsigned*>(&h23);
        reinterpret_cast<uint2*>(g_xfh)[(size_t)n * 32 + lane] = pk;
    }
    if (lane == 0) atomicAdd(&sLoss, lacc);
    __syncthreads();
    if (threadIdx.x == 0) atomicAdd(&g_loss, sLoss);
}

__device__ __forceinline__ float dot8h(uint4 a, uint4 b) {
    const unsigned* pa = &a.x;
    const unsigned* pb = &b.x;
    float s = 0.0f;
#pragma unroll
    for (int i = 0; i < 4; ++i) {
        float2 fa = __half22float2(*reinterpret_cast<const __half2*>(pa + i));
        float2 fb = __half22float2(*reinterpret_cast<const __half2*>(pb + i));
        s += fa.x * fb.x + fa.y * fb.y;
    }
    return s;
}

// half-warp (16 lanes) per prompt-edge on fp16 xf: w = relu(dot); track max
__global__ void k_edge(const int* __restrict__ prow, const int* __restrict__ pcol,
                       float* __restrict__ outw) {
    __shared__ unsigned int smax;
    if (threadIdx.x == 0) smax = 0u;
    __syncthreads();
    int t    = threadIdx.x;
    int lane = t & 31;
    int sub  = lane >> 4;
    int sl   = lane & 15;
    int wid  = (blockIdx.x * blockDim.x + t) >> 5;
    int nW   = (gridDim.x * blockDim.x) >> 5;
    const uint4* xf4 = reinterpret_cast<const uint4*>(g_xfh);
    float lmax = 0.0f;
    for (int e0 = wid * 2; e0 < cfg::EPT; e0 += nW * 2) {
        int e = e0 + sub;
        float ts = 0.0f;
        bool act = (e < cfg::EPT);
        if (act) {
            int r = prow[e], c = pcol[e];
            uint4 av = xf4[(size_t)r * 16 + sl];
            uint4 bv = xf4[(size_t)c * 16 + sl];
            ts = dot8h(av, bv);
        }
#pragma unroll
        for (int o = 8; o; o >>= 1) ts += __shfl_xor_sync(0xffffffffu, ts, o);
        if (sl == 0 && act) {
            float wv = fmaxf(ts, 0.0f);
            outw[e] = wv;
            lmax = fmaxf(lmax, wv);
        }
    }
    atomicMax(&smax, __float_as_uint(lmax));
    __syncthreads();
    if (threadIdx.x == 0) atomicMax(&g_wmax, smax);
}

// scale w in place; emit ot_loss
__global__ void k_scale(float* __restrict__ out) {
    float inv = 1.0f / (__uint_as_float(g_wmax) + 1e-8f);
    float* w = out + (size_t)cfg::N * cfg::D + 1;
    size_t idx    = (size_t)blockIdx.x * blockDim.x + threadIdx.x;
    size_t stride = (size_t)gridDim.x * blockDim.x;
    for (size_t e = idx; e < (size_t)cfg::EPT; e += stride) w[e] *= inv;
    if (blockIdx.x == 0 && threadIdx.x == 0) out[(size_t)cfg::N * cfg::D] = g_loss;
}

// ---------------- launch ----------------
extern "C" void kernel_launch(void* const* d_in, const int* in_sizes, int n_in,
                              void* d_out, int out_size) {
    const float* x     = (const float*)d_in[0];
    const int*   ei    = (const int*)d_in[1];
    const float* ew    = (const float*)d_in[2];
    const int*   pei   = (const int*)d_in[3];
    const float* pt    = (const float*)d_in[4];
    const float* alpha = (const float*)d_in[5];
    const float* gamma = (const float*)d_in[6];
    float* out = (float*)d_out;

    const int* row  = ei;
    const int* col  = ei + cfg::E;
    const int* prow = pei;
    const int* pcol = pei + cfg::EPT;

    cudaFuncSetAttribute(k_ck, cudaFuncAttributeMaxDynamicSharedMemorySize, 98304);

    k_zero<<<512, 256>>>();
    k_xh<<<2048, 256>>>(x);
    k_count<<<(cfg::E + 255) / 256, 256>>>(row, col);
    k_node<<<(cfg::N + 255) / 256, 256>>>();
    k_fill<<<(cfg::E + 255) / 256, 256>>>(row, col, ew);
    k_aggr<<<(cfg::N * 32 + 255) / 256, 256>>>();
    k_pn<<<1, 256>>>(pt);
    k_ck<<<(cfg::N + 127) / 128, 256, 98304>>>(x, gamma);

    k_sink<<<SBLK, STHR>>>();

    k_final<<<2048, 256>>>(x, pt, alpha, out);
    k_edge<<<8192, 256>>>(prow, pcol, out + (size_t)cfg::N * cfg::D + 1);
    k_scale<<<4096, 256>>>(out);
}

// round 5
// speedup vs baseline: 1.9778x; 1.1140x over previous
#include <cuda_runtime.h>
#include <cuda_fp16.h>
#include <cstdint>

// ---------------- problem constants ----------------
namespace cfg {
constexpr int   N    = 100000;
constexpr int   D    = 128;
constexpr int   P    = 64;
constexpr int   E    = 3200000;
constexpr int   EPT  = 5000000;
constexpr float INV_EPS = 10.0f;           // 1/0.1
constexpr int   ITERS   = 20;
constexpr float A_MARG  = 1.0f / 100000.0f;
constexpr float B_MARG  = 1.0f / 64.0f;
}

// ---------------- device scratch (static, no allocs) ----------------
__device__ int   g_cnt[cfg::N];                      // row histogram (CSR)
__device__ int   g_degc[cfg::N];                     // col histogram (GCN deg)
__device__ float g_dis[cfg::N];                      // deg^-1/2
__device__ int   g_off[cfg::N];                      // CSR segment base
__device__ int   g_cursor[cfg::N];                   // CSR fill cursor
__device__ int2  g_epay[cfg::E];                     // CSR payload: (col, nw-bits)
__device__ int   g_total;                            // segment allocator
__device__ __half g_xh[(size_t)cfg::N * cfg::D];     // fp16 copy of x (gathers)
__device__ float g_aggr[(size_t)cfg::N * cfg::D];    // aggregation result
__device__ __half g_xfh[(size_t)cfg::N * cfg::D];    // normalized x_adapted (fp16)
__device__ float g_K[(size_t)cfg::P * cfg::N];       // column-major K[p][n]
__device__ float g_S[(size_t)cfg::P * cfg::N];       // column-major cos sim s[p][n]
__device__ float g_u[cfg::N];
__device__ float g_KtuI[cfg::ITERS + 1][cfg::P];     // per-iteration K^T u buffers
__device__ float g_v[cfg::P];
__device__ float g_pn[cfg::P * cfg::D];              // normalized prompts
__device__ float g_loss;
__device__ unsigned int g_wmax;

// ---------------- helpers ----------------
__device__ __forceinline__ float warpAllReduceSum(float v) {
#pragma unroll
    for (int o = 16; o; o >>= 1) v += __shfl_xor_sync(0xffffffffu, v, o);
    return v;
}

// ---------------- kernels ----------------

__global__ void k_zero() {
    size_t idx    = (size_t)blockIdx.x * blockDim.x + threadIdx.x;
    size_t stride = (size_t)gridDim.x * blockDim.x;
    for (size_t i = idx; i < (size_t)cfg::N; i += stride) { g_cnt[i] = 0; g_degc[i] = 0; }
    if (idx < (size_t)((cfg::ITERS + 1) * cfg::P))
        g_KtuI[idx / cfg::P][idx % cfg::P] = 0.0f;
    if (idx == 0) { g_loss = 0.0f; g_wmax = 0u; g_total = 0; }
}

// fp16 copy of x for gather traffic reduction
__global__ void k_xh(const float* __restrict__ x) {
    size_t idx    = (size_t)blockIdx.x * blockDim.x + threadIdx.x;
    size_t stride = (size_t)gridDim.x * blockDim.x;
    const float4* x4 = reinterpret_cast<const float4*>(x);
    uint2* xh2 = reinterpret_cast<uint2*>(g_xh);
    size_t total = (size_t)cfg::N * cfg::D / 4;
    for (size_t i = idx; i < total; i += stride) {
        float4 v = x4[i];
        __half2 h0 = __floats2half2_rn(v.x, v.y);
        __half2 h1 = __floats2half2_rn(v.z, v.w);
        uint2 pk;
        pk.x = *reinterpret_cast<unsigned*>(&h0);
        pk.y = *reinterpret_cast<unsigned*>(&h1);
        xh2[i] = pk;
    }
}

// histograms: row buckets (CSR) and col degree (GCN norm)
__global__ void k_count(const int* __restrict__ row, const int* __restrict__ col) {
    int i = blockIdx.x * blockDim.x + threadIdx.x;
    if (i < cfg::E) {
        atomicAdd(&g_cnt[row[i]], 1);
        atomicAdd(&g_degc[col[i]], 1);
    }
}

// per node: deg^-1/2 and CSR segment allocation (ticket; order irrelevant)
__global__ void k_node() {
    int i = blockIdx.x * blockDim.x + threadIdx.x;
    if (i < cfg::N) {
        int d = g_degc[i];
        g_dis[i] = (d > 0) ? rsqrtf((float)d) : 0.0f;
        int c = g_cnt[i];
        int base = atomicAdd(&g_total, c);
        g_off[i] = base;
        g_cursor[i] = base;
    }
}

// per edge: compute normalized weight, drop packed payload into row's CSR segment
__global__ void k_fill(const int* __restrict__ row, const int* __restrict__ col,
                       const float* __restrict__ ew) {
    int i = blockIdx.x * blockDim.x + threadIdx.x;
    if (i < cfg::E) {
        int r = row[i], c = col[i];
        float nw = g_dis[r] * ew[i] * g_dis[c];
        int pos = atomicAdd(&g_cursor[r], 1);
        g_epay[pos] = make_int2(c, __float_as_int(nw));
    }
}

// warp per node: pull-aggregate xh[col]*nw over the node's CSR segment.
// 4-deep unroll, independent accumulators for MLP.
__global__ void k_aggr() {
    int lane = threadIdx.x & 31;
    int n    = (blockIdx.x * blockDim.x + threadIdx.x) >> 5;
    if (n >= cfg::N) return;
    int base = g_off[n];
    int cnt  = g_cnt[n];
    const uint2* xh2 = reinterpret_cast<const uint2*>(g_xh);
    float4 a0 = make_float4(0.f, 0.f, 0.f, 0.f);
    float4 a1 = make_float4(0.f, 0.f, 0.f, 0.f);
    int j = 0;
    for (; j + 4 <= cnt; j += 4) {
        int2 p0 = g_epay[base + j];
        int2 p1 = g_epay[base + j + 1];
        int2 p2 = g_epay[base + j + 2];
        int2 p3 = g_epay[base + j + 3];
        uint2 r0 = __ldg(&xh2[(size_t)p0.x * 32 + lane]);
        uint2 r1 = __ldg(&xh2[(size_t)p1.x * 32 + lane]);
        uint2 r2 = __ldg(&xh2[(size_t)p2.x * 32 + lane]);
        uint2 r3 = __ldg(&xh2[(size_t)p3.x * 32 + lane]);
        float w0 = __int_as_float(p0.y), w1 = __int_as_float(p1.y);
        float w2 = __int_as_float(p2.y), w3 = __int_as_float(p3.y);
        float2 f;
        f = __half22float2(*reinterpret_cast<__half2*>(&r0.x)); a0.x += w0*f.x; a0.y += w0*f.y;
        f = __half22float2(*reinterpret_cast<__half2*>(&r0.y)); a0.z += w0*f.x; a0.w += w0*f.y;
        f = __half22float2(*reinterpret_cast<__half2*>(&r1.x)); a1.x += w1*f.x; a1.y += w1*f.y;
        f = __half22float2(*reinterpret_cast<__half2*>(&r1.y)); a1.z += w1*f.x; a1.w += w1*f.y;
        f = __half22float2(*reinterpret_cast<__half2*>(&r2.x)); a0.x += w2*f.x; a0.y += w2*f.y;
        f = __half22float2(*reinterpret_cast<__half2*>(&r2.y)); a0.z += w2*f.x; a0.w += w2*f.y;
        f = __half22float2(*reinterpret_cast<__half2*>(&r3.x)); a1.x += w3*f.x; a1.y += w3*f.y;
        f = __half22float2(*reinterpret_cast<__half2*>(&r3.y)); a1.z += w3*f.x; a1.w += w3*f.y;
    }
    for (; j < cnt; ++j) {
        int2 p0 = g_epay[base + j];
        uint2 r0 = __ldg(&xh2[(size_t)p0.x * 32 + lane]);
        float w0 = __int_as_float(p0.y);
        float2 f;
        f = __half22float2(*reinterpret_cast<__half2*>(&r0.x)); a0.x += w0*f.x; a0.y += w0*f.y;
        f = __half22float2(*reinterpret_cast<__half2*>(&r0.y)); a0.z += w0*f.x; a0.w += w0*f.y;
    }
    float4 acc = make_float4(a0.x + a1.x, a0.y + a1.y, a0.z + a1.z, a0.w + a1.w);
    reinterpret_cast<float4*>(g_aggr)[(size_t)n * 32 + lane] = acc;
}

// normalize prompt tokens (single block)
__global__ void k_pn(const float* __restrict__ pt) {
    int lane = threadIdx.x & 31;
    int w    = threadIdx.x >> 5;
    for (int p = w; p < cfg::P; p += blockDim.x / 32) {
        float4 v = reinterpret_cast<const float4*>(pt + (size_t)p * cfg::D)[lane];
        float ss = warpAllReduceSum(v.x * v.x + v.y * v.y + v.z * v.z + v.w * v.w);
        float inv = 1.0f / fmaxf(sqrtf(ss), 1e-12f);
        float4 o = make_float4(v.x * inv, v.y * inv, v.z * inv, v.w * inv);
        reinterpret_cast<float4*>(g_pn + (size_t)p * cfg::D)[lane] = o;
    }
}

// Fused: per block of 128 nodes, build normalized xs in swizzled smem, then
// register-tiled GEMM against pn -> K (exp) and raw cos s, column-major.
__global__ void k_ck(const float* __restrict__ x, const float* __restrict__ gammap) {
    extern __shared__ float sm[];
    float* xs_s = sm;            // 128*128
    float* pn_s = sm + 16384;    // 128*64
    int t  = threadIdx.x;
    int nb = blockIdx.x * 128;
    float gm = *gammap;

    for (int idx = t; idx < cfg::P * cfg::D; idx += 256) {
        int p = idx >> 7, d = idx & 127;
        pn_s[d * 64 + p] = g_pn[idx];
    }

    int lane = t & 31, w = t >> 5;
    for (int it = 0; it < 16; ++it) {
        int nl = w + 8 * it;
        int n  = nb + nl;
        bool act = (n < cfg::N);
        float xs[4];
        float ss = 0.0f;
#pragma unroll
        for (int m = 0; m < 4; ++m) {
            int d = lane + 32 * m;
            float xv = act ? x[(size_t)n * 128 + d] : 0.0f;
            float ag = act ? g_aggr[(size_t)n * 128 + d] : 0.0f;
            xs[m] = (1.0f - gm) * xv + gm * ag;
            ss += xs[m] * xs[m];
        }
        ss = warpAllReduceSum(ss);
        float inv = 1.0f / fmaxf(sqrtf(ss), 1e-12f);
#pragma unroll
        for (int m = 0; m < 4; ++m) {
            int d = lane + 32 * m;
            xs_s[d * 128 + ((nl + d) & 127)] = xs[m] * inv;
        }
    }
    __syncthreads();

    int tx = t & 31, ty = t >> 5;
    float acc[4][8];
#pragma unroll
    for (int i = 0; i < 4; ++i)
#pragma unroll
        for (int j = 0; j < 8; ++j) acc[i][j] = 0.0f;

#pragma unroll 4
    for (int k = 0; k < 128; ++k) {
        float a[4];
#pragma unroll
        for (int i = 0; i < 4; ++i)
            a[i] = xs_s[k * 128 + ((tx + 32 * i + k) & 127)];
        float b[8];
#pragma unroll
        for (int j = 0; j < 8; ++j)
            b[j] = pn_s[k * 64 + ty * 8 + j];
#pragma unroll
        for (int i = 0; i < 4; ++i)
#pragma unroll
            for (int j = 0; j < 8; ++j)
                acc[i][j] += a[i] * b[j];
    }

#pragma unroll
    for (int i = 0; i < 4; ++i) {
        int n = nb + tx + 32 * i;
        if (n < cfg::N) {
#pragma unroll
            for (int j = 0; j < 8; ++j) {
                int p = ty * 8 + j;
                float s = acc[i][j];
                g_K[(size_t)p * cfg::N + n] = __expf((s - 1.0f) * cfg::INV_EPS);
                g_S[(size_t)p * cfg::N + n] = s;
            }
        }
    }
}

// One Sinkhorn pass per launch. j=0: Ktu[0]=K^T a. j=1..19: v,u,Ktu[j].
// j=20: final v (-> g_v) and u (-> g_u) only.
__global__ void k_ua(int j) {
    __shared__ float sv[cfg::P];
    __shared__ float sKtu[cfg::P];
    int t = threadIdx.x;
    if (t < cfg::P) {
        sKtu[t] = 0.0f;
        if (j > 0) {
            float v = cfg::B_MARG / (g_KtuI[j - 1][t] + 1e-30f);
            sv[t] = v;
            if (j == cfg::ITERS && blockIdx.x == 0) g_v[t] = v;
        }
    }
    __syncthreads();

    int n = blockIdx.x * 256 + t;
    bool act = (n < cfg::N);
    int nn = act ? n : 0;

    float kreg[64];
#pragma unroll
    for (int p = 0; p < 64; ++p) kreg[p] = g_K[(size_t)p * cfg::N + nn];

    float u;
    if (j == 0) {
        u = cfg::A_MARG;
    } else {
        float kv = 0.0f;
#pragma unroll
        for (int p = 0; p < 64; ++p) kv += kreg[p] * sv[p];
        u = cfg::A_MARG / (kv + 1e-30f);
    }
    if (j == cfg::ITERS) {
        if (act) g_u[n] = u;
        return;
    }
    float ua = act ? u : 0.0f;
#pragma unroll
    for (int p = 0; p < 64; ++p) kreg[p] *= ua;

    int lane = t & 31;
#pragma unroll
    for (int k = 0; k < 5; ++k) {
        int off = 16 >> k;
        int c   = 32 >> k;
        bool up = (lane & off) != 0;
#pragma unroll
        for (int i = 0; i < 32; ++i) {
            if (i < c) {
                float mine  = up ? kreg[i + c] : kreg[i];
                float other = up ? kreg[i]     : kreg[i + c];
                kreg[i] = mine + __shfl_xor_sync(0xffffffffu, other, off);
            }
        }
    }
    atomicAdd(&sKtu[2 * lane],     kreg[0]);
    atomicAdd(&sKtu[2 * lane + 1], kreg[1]);
    __syncthreads();
    if (t < cfg::P) atomicAdd(&g_KtuI[j][t], sKtu[t]);
}

// warp per node: prompt message, ot_loss, x_adapted -> out, xf(half) = l2norm.
// Reads only s; recomputes k = exp((s-1)*10) and c = 1-s.
__global__ void k_final(const float* __restrict__ x, const float* __restrict__ pt,
                        const float* __restrict__ alphap, float* __restrict__ out) {
    __shared__ float spt[cfg::P * cfg::D];
    __shared__ float sv[cfg::P];
    __shared__ float sLoss;
    for (int i = threadIdx.x; i < cfg::P * cfg::D; i += blockDim.x) spt[i] = pt[i];
    if (threadIdx.x < cfg::P) sv[threadIdx.x] = g_v[threadIdx.x];
    if (threadIdx.x == 0) sLoss = 0.0f;
    __syncthreads();
    float coef = (*alphap) * (float)cfg::N;
    int lane   = threadIdx.x & 31;
    int warpId = (blockIdx.x * blockDim.x + threadIdx.x) >> 5;
    int nWarps = (gridDim.x * blockDim.x) >> 5;
    const float4* spt4 = reinterpret_cast<const float4*>(spt);
    float lacc = 0.0f;
    for (int n = warpId; n < cfg::N; n += nWarps) {
        float u = g_u[n];
        float4 m = make_float4(0.f, 0.f, 0.f, 0.f);
        float lossn = 0.0f;
#pragma unroll 8
        for (int p = 0; p < cfg::P; p++) {
            float s  = g_S[(size_t)p * cfg::N + n];      // broadcast
            float kv = __expf((s - 1.0f) * cfg::INV_EPS) * sv[p];
            float4 pv = spt4[p * 32 + lane];
            m.x += kv * pv.x; m.y += kv * pv.y; m.z += kv * pv.z; m.w += kv * pv.w;
            lossn += kv * (1.0f - s);
        }
        lacc += u * lossn;
        float4 xv = reinterpret_cast<const float4*>(x + (size_t)n * cfg::D)[lane];
        float cu = coef * u;
        float4 xa = make_float4(xv.x + cu * m.x, xv.y + cu * m.y,
                                xv.z + cu * m.z, xv.w + cu * m.w);
        reinterpret_cast<float4*>(out + (size_t)n * cfg::D)[lane] = xa;
        float ss = warpAllReduceSum(xa.x * xa.x + xa.y * xa.y + xa.z * xa.z + xa.w * xa.w);
        float inv = 1.0f / fmaxf(sqrtf(ss), 1e-12f);
        __half2 h01 = __floats2half2_rn(xa.x * inv, xa.y * inv);
        __half2 h23 = __floats2half2_rn(xa.z * inv, xa.w * inv);
        uint2 pk;
        pk.x = *reinterpret_cast<unsigned*>(&h01);
        pk.y = *reinterpret_cast<unsigned*>(&h23);
        reinterpret_cast<uint2*>(g_xfh)[(size_t)n * 32 + lane] = pk;
    }
    if (lane == 0) atomicAdd(&sLoss, lacc);
    __syncthreads();
    if (threadIdx.x == 0) atomicAdd(&g_loss, sLoss);
}

__device__ __forceinline__ float dot8h(uint4 a, uint4 b) {
    const unsigned* pa = &a.x;
    const unsigned* pb = &b.x;
    float s = 0.0f;
#pragma unroll
    for (int i = 0; i < 4; ++i) {
        float2 fa = __half22float2(*reinterpret_cast<const __half2*>(pa + i));
        float2 fb = __half22float2(*reinterpret_cast<const __half2*>(pb + i));
        s += fa.x * fb.x + fa.y * fb.y;
    }
    return s;
}

// half-warp (16 lanes) per prompt-edge on fp16 xf: w = relu(dot); track max
__global__ void k_edge(const int* __restrict__ prow, const int* __restrict__ pcol,
                       float* __restrict__ outw) {
    __shared__ unsigned int smax;
    if (threadIdx.x == 0) smax = 0u;
    __syncthreads();
    int t    = threadIdx.x;
    int lane = t & 31;
    int sub  = lane >> 4;
    int sl   = lane & 15;
    int wid  = (blockIdx.x * blockDim.x + t) >> 5;
    int nW   = (gridDim.x * blockDim.x) >> 5;
    const uint4* xf4 = reinterpret_cast<const uint4*>(g_xfh);
    float lmax = 0.0f;
    for (int e0 = wid * 2; e0 < cfg::EPT; e0 += nW * 2) {
        int e = e0 + sub;
        float ts = 0.0f;
        bool act = (e < cfg::EPT);
        if (act) {
            int r = prow[e], c = pcol[e];
            uint4 av = __ldg(&xf4[(size_t)r * 16 + sl]);
            uint4 bv = __ldg(&xf4[(size_t)c * 16 + sl]);
            ts = dot8h(av, bv);
        }
#pragma unroll
        for (int o = 8; o; o >>= 1) ts += __shfl_xor_sync(0xffffffffu, ts, o);
        if (sl == 0 && act) {
            float wv = fmaxf(ts, 0.0f);
            outw[e] = wv;
            lmax = fmaxf(lmax, wv);
        }
    }
    atomicMax(&smax, __float_as_uint(lmax));
    __syncthreads();
    if (threadIdx.x == 0) atomicMax(&g_wmax, smax);
}

// scale w in place; emit ot_loss
__global__ void k_scale(float* __restrict__ out) {
    float inv = 1.0f / (__uint_as_float(g_wmax) + 1e-8f);
    float* w = out + (size_t)cfg::N * cfg::D + 1;
    size_t idx    = (size_t)blockIdx.x * blockDim.x + threadIdx.x;
    size_t stride = (size_t)gridDim.x * blockDim.x;
    for (size_t e = idx; e < (size_t)cfg::EPT; e += stride) w[e] *= inv;
    if (blockIdx.x == 0 && threadIdx.x == 0) out[(size_t)cfg::N * cfg::D] = g_loss;
}

// ---------------- launch ----------------
extern "C" void kernel_launch(void* const* d_in, const int* in_sizes, int n_in,
                              void* d_out, int out_size) {
    const float* x     = (const float*)d_in[0];
    const int*   ei    = (const int*)d_in[1];
    const float* ew    = (const float*)d_in[2];
    const int*   pei   = (const int*)d_in[3];
    const float* pt    = (const float*)d_in[4];
    const float* alpha = (const float*)d_in[5];
    const float* gamma = (const float*)d_in[6];
    float* out = (float*)d_out;

    const int* row  = ei;
    const int* col  = ei + cfg::E;
    const int* prow = pei;
    const int* pcol = pei + cfg::EPT;

    cudaFuncSetAttribute(k_ck, cudaFuncAttributeMaxDynamicSharedMemorySize, 98304);

    k_zero<<<512, 256>>>();
    k_xh<<<2048, 256>>>(x);
    k_count<<<(cfg::E + 255) / 256, 256>>>(row, col);
    k_node<<<(cfg::N + 255) / 256, 256>>>();
    k_fill<<<(cfg::E + 255) / 256, 256>>>(row, col, ew);
    k_aggr<<<(cfg::N * 32 + 255) / 256, 256>>>();
    k_pn<<<1, 256>>>(pt);
    k_ck<<<(cfg::N + 127) / 128, 256, 98304>>>(x, gamma);

    for (int j = 0; j <= cfg::ITERS; ++j)
        k_ua<<<(cfg::N + 255) / 256, 256>>>(j);

    k_final<<<2048, 256>>>(x, pt, alpha, out);
    k_edge<<<8192, 256>>>(prow, pcol, out + (size_t)cfg::N * cfg::D + 1);
    k_scale<<<4096, 256>>>(out);
}

// round 6
// speedup vs baseline: 2.0422x; 1.0326x over previous
#include <cuda_runtime.h>
#include <cuda_fp16.h>
#include <cstdint>

// ---------------- problem constants ----------------
namespace cfg {
constexpr int   N    = 100000;
constexpr int   D    = 128;
constexpr int   P    = 64;
constexpr int   E    = 3200000;
constexpr int   EPT  = 5000000;
constexpr float INV_EPS = 10.0f;           // 1/0.1
constexpr int   ITERS   = 20;
constexpr float A_MARG  = 1.0f / 100000.0f;
constexpr float B_MARG  = 1.0f / 64.0f;
}

// ---------------- device scratch (static, no allocs) ----------------
__device__ int   g_cnt[cfg::N];                      // row histogram (CSR)
__device__ int   g_degc[cfg::N];                     // col histogram (GCN deg)
__device__ float g_dis[cfg::N];                      // deg^-1/2
__device__ int   g_off[cfg::N];                      // CSR segment base
__device__ int   g_cursor[cfg::N];                   // CSR fill cursor
__device__ int2  g_epay[cfg::E];                     // CSR payload: (col, nw-bits)
__device__ int   g_total;                            // segment allocator
__device__ __half g_xh[(size_t)cfg::N * cfg::D];     // fp16 copy of x (gathers)
__device__ float g_aggr[(size_t)cfg::N * cfg::D];    // aggregation result
__device__ __half g_xfh[(size_t)cfg::N * cfg::D];    // normalized x_adapted (fp16)
__device__ unsigned g_Kh[(size_t)(cfg::P / 2) * cfg::N]; // half2 K: [k][n], p=(2k,2k+1)
__device__ float g_u[cfg::N];
__device__ float g_KtuI[cfg::ITERS + 1][cfg::P];     // per-iteration K^T u buffers
__device__ float g_v[cfg::P];
__device__ float g_pn[cfg::P * cfg::D];              // normalized prompts
__device__ float g_loss;
__device__ unsigned int g_wmax;

// ---------------- helpers ----------------
__device__ __forceinline__ float warpAllReduceSum(float v) {
#pragma unroll
    for (int o = 16; o; o >>= 1) v += __shfl_xor_sync(0xffffffffu, v, o);
    return v;
}

// ---------------- kernels ----------------

__global__ void k_zero() {
    size_t idx    = (size_t)blockIdx.x * blockDim.x + threadIdx.x;
    size_t stride = (size_t)gridDim.x * blockDim.x;
    for (size_t i = idx; i < (size_t)cfg::N; i += stride) { g_cnt[i] = 0; g_degc[i] = 0; }
    if (idx < (size_t)((cfg::ITERS + 1) * cfg::P))
        g_KtuI[idx / cfg::P][idx % cfg::P] = 0.0f;
    if (idx == 0) { g_loss = 0.0f; g_wmax = 0u; g_total = 0; }
}

// fp16 copy of x for gather traffic reduction
__global__ void k_xh(const float* __restrict__ x) {
    size_t idx    = (size_t)blockIdx.x * blockDim.x + threadIdx.x;
    size_t stride = (size_t)gridDim.x * blockDim.x;
    const float4* x4 = reinterpret_cast<const float4*>(x);
    uint2* xh2 = reinterpret_cast<uint2*>(g_xh);
    size_t total = (size_t)cfg::N * cfg::D / 4;
    for (size_t i = idx; i < total; i += stride) {
        float4 v = x4[i];
        __half2 h0 = __floats2half2_rn(v.x, v.y);
        __half2 h1 = __floats2half2_rn(v.z, v.w);
        uint2 pk;
        pk.x = *reinterpret_cast<unsigned*>(&h0);
        pk.y = *reinterpret_cast<unsigned*>(&h1);
        xh2[i] = pk;
    }
}

// histograms: row buckets (CSR) and col degree (GCN norm)
__global__ void k_count(const int* __restrict__ row, const int* __restrict__ col) {
    int i = blockIdx.x * blockDim.x + threadIdx.x;
    if (i < cfg::E) {
        atomicAdd(&g_cnt[row[i]], 1);
        atomicAdd(&g_degc[col[i]], 1);
    }
}

// per node: deg^-1/2 and CSR segment allocation (ticket; order irrelevant)
__global__ void k_node() {
    int i = blockIdx.x * blockDim.x + threadIdx.x;
    if (i < cfg::N) {
        int d = g_degc[i];
        g_dis[i] = (d > 0) ? rsqrtf((float)d) : 0.0f;
        int c = g_cnt[i];
        int base = atomicAdd(&g_total, c);
        g_off[i] = base;
        g_cursor[i] = base;
    }
}

// per edge: compute normalized weight, drop packed payload into row's CSR segment
__global__ void k_fill(const int* __restrict__ row, const int* __restrict__ col,
                       const float* __restrict__ ew) {
    int i = blockIdx.x * blockDim.x + threadIdx.x;
    if (i < cfg::E) {
        int r = row[i], c = col[i];
        float nw = g_dis[r] * ew[i] * g_dis[c];
        int pos = atomicAdd(&g_cursor[r], 1);
        g_epay[pos] = make_int2(c, __float_as_int(nw));
    }
}

// warp per node: pull-aggregate xh[col]*nw over the node's CSR segment.
__global__ void k_aggr() {
    int lane = threadIdx.x & 31;
    int n    = (blockIdx.x * blockDim.x + threadIdx.x) >> 5;
    if (n >= cfg::N) return;
    int base = g_off[n];
    int cnt  = g_cnt[n];
    const uint2* xh2 = reinterpret_cast<const uint2*>(g_xh);
    float4 a0 = make_float4(0.f, 0.f, 0.f, 0.f);
    float4 a1 = make_float4(0.f, 0.f, 0.f, 0.f);
    int j = 0;
    for (; j + 4 <= cnt; j += 4) {
        int2 p0 = g_epay[base + j];
        int2 p1 = g_epay[base + j + 1];
        int2 p2 = g_epay[base + j + 2];
        int2 p3 = g_epay[base + j + 3];
        uint2 r0 = __ldg(&xh2[(size_t)p0.x * 32 + lane]);
        uint2 r1 = __ldg(&xh2[(size_t)p1.x * 32 + lane]);
        uint2 r2 = __ldg(&xh2[(size_t)p2.x * 32 + lane]);
        uint2 r3 = __ldg(&xh2[(size_t)p3.x * 32 + lane]);
        float w0 = __int_as_float(p0.y), w1 = __int_as_float(p1.y);
        float w2 = __int_as_float(p2.y), w3 = __int_as_float(p3.y);
        float2 f;
        f = __half22float2(*reinterpret_cast<__half2*>(&r0.x)); a0.x += w0*f.x; a0.y += w0*f.y;
        f = __half22float2(*reinterpret_cast<__half2*>(&r0.y)); a0.z += w0*f.x; a0.w += w0*f.y;
        f = __half22float2(*reinterpret_cast<__half2*>(&r1.x)); a1.x += w1*f.x; a1.y += w1*f.y;
        f = __half22float2(*reinterpret_cast<__half2*>(&r1.y)); a1.z += w1*f.x; a1.w += w1*f.y;
        f = __half22float2(*reinterpret_cast<__half2*>(&r2.x)); a0.x += w2*f.x; a0.y += w2*f.y;
        f = __half22float2(*reinterpret_cast<__half2*>(&r2.y)); a0.z += w2*f.x; a0.w += w2*f.y;
        f = __half22float2(*reinterpret_cast<__half2*>(&r3.x)); a1.x += w3*f.x; a1.y += w3*f.y;
        f = __half22float2(*reinterpret_cast<__half2*>(&r3.y)); a1.z += w3*f.x; a1.w += w3*f.y;
    }
    for (; j < cnt; ++j) {
        int2 p0 = g_epay[base + j];
        uint2 r0 = __ldg(&xh2[(size_t)p0.x * 32 + lane]);
        float w0 = __int_as_float(p0.y);
        float2 f;
        f = __half22float2(*reinterpret_cast<__half2*>(&r0.x)); a0.x += w0*f.x; a0.y += w0*f.y;
        f = __half22float2(*reinterpret_cast<__half2*>(&r0.y)); a0.z += w0*f.x; a0.w += w0*f.y;
    }
    float4 acc = make_float4(a0.x + a1.x, a0.y + a1.y, a0.z + a1.z, a0.w + a1.w);
    reinterpret_cast<float4*>(g_aggr)[(size_t)n * 32 + lane] = acc;
}

// normalize prompt tokens (single block)
__global__ void k_pn(const float* __restrict__ pt) {
    int lane = threadIdx.x & 31;
    int w    = threadIdx.x >> 5;
    for (int p = w; p < cfg::P; p += blockDim.x / 32) {
        float4 v = reinterpret_cast<const float4*>(pt + (size_t)p * cfg::D)[lane];
        float ss = warpAllReduceSum(v.x * v.x + v.y * v.y + v.z * v.z + v.w * v.w);
        float inv = 1.0f / fmaxf(sqrtf(ss), 1e-12f);
        float4 o = make_float4(v.x * inv, v.y * inv, v.z * inv, v.w * inv);
        reinterpret_cast<float4*>(g_pn + (size_t)p * cfg::D)[lane] = o;
    }
}

// Fused: per block of 128 nodes, build normalized xs in swizzled smem, then
// register-tiled GEMM against pn -> packed half2 K. Also accumulates
// Sinkhorn iteration 0 (Ktu0 = a * colsum(K)) in the epilogue.
__global__ void k_ck(const float* __restrict__ x, const float* __restrict__ gammap) {
    extern __shared__ float sm[];
    float* xs_s = sm;            // 128*128
    float* pn_s = sm + 16384;    // 128*64
    int t  = threadIdx.x;
    int nb = blockIdx.x * 128;
    float gm = *gammap;

    for (int idx = t; idx < cfg::P * cfg::D; idx += 256) {
        int p = idx >> 7, d = idx & 127;
        pn_s[d * 64 + p] = g_pn[idx];
    }

    int lane = t & 31, w = t >> 5;
    for (int it = 0; it < 16; ++it) {
        int nl = w + 8 * it;
        int n  = nb + nl;
        bool act = (n < cfg::N);
        float xs[4];
        float ss = 0.0f;
#pragma unroll
        for (int m = 0; m < 4; ++m) {
            int d = lane + 32 * m;
            float xv = act ? x[(size_t)n * 128 + d] : 0.0f;
            float ag = act ? g_aggr[(size_t)n * 128 + d] : 0.0f;
            xs[m] = (1.0f - gm) * xv + gm * ag;
            ss += xs[m] * xs[m];
        }
        ss = warpAllReduceSum(ss);
        float inv = 1.0f / fmaxf(sqrtf(ss), 1e-12f);
#pragma unroll
        for (int m = 0; m < 4; ++m) {
            int d = lane + 32 * m;
            xs_s[d * 128 + ((nl + d) & 127)] = xs[m] * inv;
        }
    }
    __syncthreads();

    int tx = t & 31, ty = t >> 5;
    float acc[4][8];
#pragma unroll
    for (int i = 0; i < 4; ++i)
#pragma unroll
        for (int j = 0; j < 8; ++j) acc[i][j] = 0.0f;

#pragma unroll 4
    for (int k = 0; k < 128; ++k) {
        float a[4];
#pragma unroll
        for (int i = 0; i < 4; ++i)
            a[i] = xs_s[k * 128 + ((tx + 32 * i + k) & 127)];
        float b[8];
#pragma unroll
        for (int j = 0; j < 8; ++j)
            b[j] = pn_s[k * 64 + ty * 8 + j];
#pragma unroll
        for (int i = 0; i < 4; ++i)
#pragma unroll
            for (int j = 0; j < 8; ++j)
                acc[i][j] += a[i] * b[j];
    }

    // epilogue: K = exp((s-1)*10) -> half2 [32][N]; accumulate Ktu0
    float ksum[8];
#pragma unroll
    for (int j = 0; j < 8; ++j) ksum[j] = 0.0f;
#pragma unroll
    for (int i = 0; i < 4; ++i) {
        int n = nb + tx + 32 * i;
        bool act = (n < cfg::N);
        float kv[8];
#pragma unroll
        for (int j = 0; j < 8; ++j) {
            kv[j] = __expf((acc[i][j] - 1.0f) * cfg::INV_EPS);
            if (act) ksum[j] += kv[j];
        }
        if (act) {
#pragma unroll
            for (int m = 0; m < 4; ++m) {
                __half2 h = __floats2half2_rn(kv[2 * m], kv[2 * m + 1]);
                g_Kh[(size_t)(ty * 4 + m) * cfg::N + n] = *reinterpret_cast<unsigned*>(&h);
            }
        }
    }
#pragma unroll
    for (int j = 0; j < 8; ++j) {
        float tot = warpAllReduceSum(ksum[j]);
        if (tx == 0) atomicAdd(&g_KtuI[0][ty * 8 + j], cfg::A_MARG * tot);
    }
}

// One Sinkhorn pass per launch, j=1..20: v = b/Ktu[j-1]; u = a/(K v);
// j<20: Ktu[j] = K^T u. j=20: store u (and v).
__global__ void k_ua(int j) {
    __shared__ float sv[cfg::P];
    __shared__ float sKtu[cfg::P];
    int t = threadIdx.x;
    if (t < cfg::P) {
        sKtu[t] = 0.0f;
        float v = cfg::B_MARG / (g_KtuI[j - 1][t] + 1e-30f);
        sv[t] = v;
        if (j == cfg::ITERS && blockIdx.x == 0) g_v[t] = v;
    }
    __syncthreads();

    int n = blockIdx.x * 256 + t;
    bool act = (n < cfg::N);
    int nn = act ? n : 0;

    float kreg[64];
#pragma unroll
    for (int k = 0; k < 32; ++k) {
        unsigned raw = g_Kh[(size_t)k * cfg::N + nn];
        float2 f = __half22float2(*reinterpret_cast<__half2*>(&raw));
        kreg[2 * k]     = f.x;
        kreg[2 * k + 1] = f.y;
    }

    float kv = 0.0f;
#pragma unroll
    for (int p = 0; p < 64; ++p) kv += kreg[p] * sv[p];
    float u = cfg::A_MARG / (kv + 1e-30f);

    if (j == cfg::ITERS) {
        if (act) g_u[n] = u;
        return;
    }
    float ua = act ? u : 0.0f;
#pragma unroll
    for (int p = 0; p < 64; ++p) kreg[p] *= ua;

    int lane = t & 31;
#pragma unroll
    for (int k = 0; k < 5; ++k) {
        int off = 16 >> k;
        int c   = 32 >> k;
        bool up = (lane & off) != 0;
#pragma unroll
        for (int i = 0; i < 32; ++i) {
            if (i < c) {
                float mine  = up ? kreg[i + c] : kreg[i];
                float other = up ? kreg[i]     : kreg[i + c];
                kreg[i] = mine + __shfl_xor_sync(0xffffffffu, other, off);
            }
        }
    }
    atomicAdd(&sKtu[2 * lane],     kreg[0]);
    atomicAdd(&sKtu[2 * lane + 1], kreg[1]);
    __syncthreads();
    if (t < cfg::P) atomicAdd(&g_KtuI[j][t], sKtu[t]);
}

// warp per node: prompt message, ot_loss, x_adapted -> out, xf(half) = l2norm.
// Reads only half2 K; reconstructs c = -0.1*ln(K).
__global__ void k_final(const float* __restrict__ x, const float* __restrict__ pt,
                        const float* __restrict__ alphap, float* __restrict__ out) {
    __shared__ float spt[cfg::P * cfg::D];
    __shared__ float sv[cfg::P];
    __shared__ float sLoss;
    for (int i = threadIdx.x; i < cfg::P * cfg::D; i += blockDim.x) spt[i] = pt[i];
    if (threadIdx.x < cfg::P) sv[threadIdx.x] = g_v[threadIdx.x];
    if (threadIdx.x == 0) sLoss = 0.0f;
    __syncthreads();
    float coef = (*alphap) * (float)cfg::N;
    int lane   = threadIdx.x & 31;
    int warpId = (blockIdx.x * blockDim.x + threadIdx.x) >> 5;
    int nWarps = (gridDim.x * blockDim.x) >> 5;
    const float4* spt4 = reinterpret_cast<const float4*>(spt);
    float lacc = 0.0f;
    for (int n = warpId; n < cfg::N; n += nWarps) {
        float u = g_u[n];
        float4 m = make_float4(0.f, 0.f, 0.f, 0.f);
        float lossn = 0.0f;
#pragma unroll 4
        for (int k = 0; k < 32; ++k) {
            unsigned raw = g_Kh[(size_t)k * cfg::N + n];   // warp broadcast
            float2 f = __half22float2(*reinterpret_cast<__half2*>(&raw));
            float kv0 = f.x * sv[2 * k];
            float kv1 = f.y * sv[2 * k + 1];
            float4 p0 = spt4[(2 * k) * 32 + lane];
            float4 p1 = spt4[(2 * k + 1) * 32 + lane];
            m.x += kv0 * p0.x + kv1 * p1.x;
            m.y += kv0 * p0.y + kv1 * p1.y;
            m.z += kv0 * p0.z + kv1 * p1.z;
            m.w += kv0 * p0.w + kv1 * p1.w;
            lossn += kv0 * (-0.1f * __logf(fmaxf(f.x, 1e-7f)))
                   + kv1 * (-0.1f * __logf(fmaxf(f.y, 1e-7f)));
        }
        lacc += u * lossn;
        float4 xv = reinterpret_cast<const float4*>(x + (size_t)n * cfg::D)[lane];
        float cu = coef * u;
        float4 xa = make_float4(xv.x + cu * m.x, xv.y + cu * m.y,
                                xv.z + cu * m.z, xv.w + cu * m.w);
        reinterpret_cast<float4*>(out + (size_t)n * cfg::D)[lane] = xa;
        float ss = warpAllReduceSum(xa.x * xa.x + xa.y * xa.y + xa.z * xa.z + xa.w * xa.w);
        float inv = 1.0f / fmaxf(sqrtf(ss), 1e-12f);
        __half2 h01 = __floats2half2_rn(xa.x * inv, xa.y * inv);
        __half2 h23 = __floats2half2_rn(xa.z * inv, xa.w * inv);
        uint2 pk;
        pk.x = *reinterpret_cast<unsigned*>(&h01);
        pk.y = *reinterpret_cast<unsigned*>(&h23);
        reinterpret_cast<uint2*>(g_xfh)[(size_t)n * 32 + lane] = pk;
    }
    if (lane == 0) atomicAdd(&sLoss, lacc);
    __syncthreads();
    if (threadIdx.x == 0) atomicAdd(&g_loss, sLoss);
}

__device__ __forceinline__ float dot8h(uint4 a, uint4 b) {
    const unsigned* pa = &a.x;
    const unsigned* pb = &b.x;
    float s = 0.0f;
#pragma unroll
    for (int i = 0; i < 4; ++i) {
        float2 fa = __half22float2(*reinterpret_cast<const __half2*>(pa + i));
        float2 fb = __half22float2(*reinterpret_cast<const __half2*>(pb + i));
        s += fa.x * fb.x + fa.y * fb.y;
    }
    return s;
}

// half-warp (16 lanes) per prompt-edge on fp16 xf: w = relu(dot); track max
__global__ void k_edge(const int* __restrict__ prow, const int* __restrict__ pcol,
                       float* __restrict__ outw) {
    __shared__ unsigned int smax;
    if (threadIdx.x == 0) smax = 0u;
    __syncthreads();
    int t    = threadIdx.x;
    int lane = t & 31;
    int sub  = lane >> 4;
    int sl   = lane & 15;
    int wid  = (blockIdx.x * blockDim.x + t) >> 5;
    int nW   = (gridDim.x * blockDim.x) >> 5;
    const uint4* xf4 = reinterpret_cast<const uint4*>(g_xfh);
    float lmax = 0.0f;
    for (int e0 = wid * 2; e0 < cfg::EPT; e0 += nW * 2) {
        int e = e0 + sub;
        float ts = 0.0f;
        bool act = (e < cfg::EPT);
        if (act) {
            int r = prow[e], c = pcol[e];
            uint4 av = __ldg(&xf4[(size_t)r * 16 + sl]);
            uint4 bv = __ldg(&xf4[(size_t)c * 16 + sl]);
            ts = dot8h(av, bv);
        }
#pragma unroll
        for (int o = 8; o; o >>= 1) ts += __shfl_xor_sync(0xffffffffu, ts, o);
        if (sl == 0 && act) {
            float wv = fmaxf(ts, 0.0f);
            outw[e] = wv;
            lmax = fmaxf(lmax, wv);
        }
    }
    atomicMax(&smax, __float_as_uint(lmax));
    __syncthreads();
    if (threadIdx.x == 0) atomicMax(&g_wmax, smax);
}

// scale w in place; emit ot_loss
__global__ void k_scale(float* __restrict__ out) {
    float inv = 1.0f / (__uint_as_float(g_wmax) + 1e-8f);
    float* w = out + (size_t)cfg::N * cfg::D + 1;
    size_t idx    = (size_t)blockIdx.x * blockDim.x + threadIdx.x;
    size_t stride = (size_t)gridDim.x * blockDim.x;
    for (size_t e = idx; e < (size_t)cfg::EPT; e += stride) w[e] *= inv;
    if (blockIdx.x == 0 && threadIdx.x == 0) out[(size_t)cfg::N * cfg::D] = g_loss;
}

// ---------------- launch ----------------
extern "C" void kernel_launch(void* const* d_in, const int* in_sizes, int n_in,
                              void* d_out, int out_size) {
    const float* x     = (const float*)d_in[0];
    const int*   ei    = (const int*)d_in[1];
    const float* ew    = (const float*)d_in[2];
    const int*   pei   = (const int*)d_in[3];
    const float* pt    = (const float*)d_in[4];
    const float* alpha = (const float*)d_in[5];
    const float* gamma = (const float*)d_in[6];
    float* out = (float*)d_out;

    const int* row  = ei;
    const int* col  = ei + cfg::E;
    const int* prow = pei;
    const int* pcol = pei + cfg::EPT;

    cudaFuncSetAttribute(k_ck, cudaFuncAttributeMaxDynamicSharedMemorySize, 98304);

    k_zero<<<512, 256>>>();
    k_xh<<<2048, 256>>>(x);
    k_count<<<(cfg::E + 255) / 256, 256>>>(row, col);
    k_node<<<(cfg::N + 255) / 256, 256>>>();
    k_fill<<<(cfg::E + 255) / 256, 256>>>(row, col, ew);
    k_aggr<<<(cfg::N * 32 + 255) / 256, 256>>>();
    k_pn<<<1, 256>>>(pt);
    k_ck<<<(cfg::N + 127) / 128, 256, 98304>>>(x, gamma);   // includes Ktu0

    for (int j = 1; j <= cfg::ITERS; ++j)
        k_ua<<<(cfg::N + 255) / 256, 256>>>(j);

    k_final<<<2048, 256>>>(x, pt, alpha, out);
    k_edge<<<8192, 256>>>(prow, pcol, out + (size_t)cfg::N * cfg::D + 1);
    k_scale<<<4096, 256>>>(out);
}